// round 11
// baseline (speedup 1.0000x reference)
#include <cuda_runtime.h>
#include <cuda_bf16.h>
#include <cstdint>
typedef long long ll;
typedef __nv_bfloat16 bf;

#define QS  8388608ll
#define LS  524288ll
#define A1S 33554432ll
#define SQS 2097152ll
#define XNS 8388608ll

__device__ __forceinline__ uint32_t smem_u32(const void* p) {
    uint32_t a;
    asm("{ .reg .u64 t; cvta.to.shared.u64 t, %1; cvt.u32.u64 %0, t; }" : "=r"(a) : "l"(p));
    return a;
}
#define LDM4(r, a) asm volatile("ldmatrix.sync.aligned.m8n8.x4.shared.b16 {%0,%1,%2,%3}, [%4];" \
    : "=r"((r)[0]), "=r"((r)[1]), "=r"((r)[2]), "=r"((r)[3]) : "r"(a))
#define MMA(c, a, b0, b1) asm volatile( \
    "mma.sync.aligned.m16n8k16.row.col.f32.bf16.bf16.f32 " \
    "{%0,%1,%2,%3}, {%4,%5,%6,%7}, {%8,%9}, {%0,%1,%2,%3};" \
    : "+f"((c)[0]), "+f"((c)[1]), "+f"((c)[2]), "+f"((c)[3]) \
    : "r"((a)[0]), "r"((a)[1]), "r"((a)[2]), "r"((a)[3]), "r"(b0), "r"(b1))
#define CPA(d, s) asm volatile("cp.async.cg.shared.global [%0], [%1], 16;" :: "r"(d), "l"(s))
#define CPC() asm volatile("cp.async.commit_group;")
#define CPW(n) asm volatile("cp.async.wait_group %0;" :: "n"(n))

__device__ __forceinline__ void splitf(float v, bf& h, bf& l) {
    h = __float2bfloat16(v);
    l = __float2bfloat16(v - __bfloat162float(h));
}
__device__ __forceinline__ float ldcg_bf(const bf* p) {
    unsigned short u;
    asm volatile("ld.global.cg.u16 %0, [%1];" : "=h"(u) : "l"(p));
    __nv_bfloat16_raw r; r.x = u;
    return __bfloat162float((bf)r);
}

// ---------- scratch ----------
__device__ bf g_xnh[XNS];
__device__ bf g_wqTh[786432], g_wqTl[786432], g_woTh[262144], g_woTl[262144];
__device__ bf g_qh[QS], g_kh[QS], g_klo[QS], g_vTh[QS], g_vTl[QS];
__device__ bf g_lqh[LS], g_lql[LS], g_lkh[LS], g_lkl[LS];
__device__ bf g_a1h[A1S], g_a3h[A1S], g_t1h[A1S];
__device__ float g_sf[A1S];
__device__ float g_a2f[SQS];
__device__ bf g_a2h[SQS], g_a2l[SQS];
__device__ bf g_xzAh[SQS], g_xzAl[SQS], g_xzTh[SQS], g_xzTl[SQS];
__device__ bf g_m1Th[SQS], g_m1Tl[SQS], g_m3Th[SQS], g_m3Tl[SQS];
__device__ bf g_zAh[2 * SQS], g_zAl[2 * SQS], g_zTh[2 * SQS], g_zTl[2 * SQS];
__device__ bf g_avTh[LS], g_avTl[LS];
__device__ float g_ohA[QS];
__device__ bf g_ohh[XNS];
__device__ int g_redi[2];
__device__ unsigned g_cnt = 0, g_gen = 0;

// ---------- reductions ----------
__device__ __forceinline__ float wrs(float v) {
    #pragma unroll
    for (int o = 16; o; o >>= 1) v += __shfl_xor_sync(0xffffffffu, v, o);
    return v;
}
__device__ __forceinline__ float wrm(float v) {
    #pragma unroll
    for (int o = 16; o; o >>= 1) v = fmaxf(v, __shfl_xor_sync(0xffffffffu, v, o));
    return v;
}
__device__ __forceinline__ float brs(float v) {
    __shared__ float sm[32];
    int lane = threadIdx.x & 31, w = threadIdx.x >> 5;
    __syncthreads();
    v = wrs(v);
    if (!lane) sm[w] = v;
    __syncthreads();
    float r = (threadIdx.x < (blockDim.x >> 5)) ? sm[threadIdx.x] : 0.f;
    if (w == 0) { r = wrs(r); if (!lane) sm[0] = r; }
    __syncthreads();
    return sm[0];
}
__device__ __forceinline__ float brm(float v) {
    __shared__ float sm[32];
    int lane = threadIdx.x & 31, w = threadIdx.x >> 5;
    __syncthreads();
    v = wrm(v);
    if (!lane) sm[w] = v;
    __syncthreads();
    float r = (threadIdx.x < (blockDim.x >> 5)) ? sm[threadIdx.x] : -3.4e38f;
    if (w == 0) { r = wrm(r); if (!lane) sm[0] = r; }
    __syncthreads();
    return sm[0];
}

// ====== HMMA GEMM, cp.async double-buffered, term-major MMA order ======
#define STR 144
template<int KIND, int NT>
__global__ __launch_bounds__(128) void tg(
    const bf* __restrict__ Ah, const bf* __restrict__ Al, ll sA,
    const bf* __restrict__ Bh, const bf* __restrict__ Bl, ll sB, int K,
    float* __restrict__ Cf, ll sC, int ldc,
    bf* __restrict__ Oh, bf* __restrict__ Ol, ll sO,
    bf* __restrict__ Th, bf* __restrict__ Tl, ll sT,
    const bf* __restrict__ Xh, const bf* __restrict__ Xl, ll sX, float c1, float c2,
    const float* __restrict__ Rf, const float* __restrict__ bias)
{
    constexpr int NARR = (NT == 3) ? 4 : (NT == 2) ? 3 : 2;
    constexpr int SSTG = NARR * 64 * STR;
    constexpr int OAL = 64 * STR;
    constexpr int OBH = (NT == 3 ? 2 : 1) * 64 * STR;
    constexpr int OBL = OBH + 64 * STR;
    extern __shared__ __align__(16) unsigned char sm_[];
    uint32_t sb = smem_u32(sm_);
    int tid = threadIdx.x, wid = tid >> 5, lane = tid & 31;
    int wy = wid >> 1, wx = wid & 1;
    int m0 = blockIdx.y * 64, n0 = blockIdx.x * 64, bz = blockIdx.z;
    Ah += (ll)bz * sA;
    if (NT == 3) Al += (ll)bz * sA;
    Bh += (ll)bz * sB;
    if (NT >= 2) Bl += (ll)bz * sB;
    float acc[2][4][4] = {};
    int row8 = tid >> 3, c8 = tid & 7;
    int nch = K >> 6;

    auto loadStage = [&](int c, int stg) {
        int k0 = c << 6;
        uint32_t base = sb + stg * SSTG;
        #pragma unroll
        for (int i = 0; i < 4; i++) {
            int r = row8 + i * 16;
            uint32_t so = r * STR + c8 * 16;
            ll ga = (ll)(m0 + r) * K + k0 + c8 * 8;
            ll gb = (ll)(n0 + r) * K + k0 + c8 * 8;
            CPA(base + so, Ah + ga);
            CPA(base + OBH + so, Bh + gb);
            if (NT == 3) CPA(base + OAL + so, Al + ga);
            if (NT >= 2) CPA(base + OBL + so, Bl + gb);
        }
    };
    loadStage(0, 0);
    CPC();
    for (int c = 0; c < nch; c++) {
        if (c + 1 < nch) { loadStage(c + 1, (c + 1) & 1); CPC(); CPW(1); }
        else CPW(0);
        __syncthreads();
        uint32_t bs = sb + (c & 1) * SSTG;
        #pragma unroll
        for (int s = 0; s < 4; s++) {
            uint32_t aH[2][4], aL[2][4], bH[4][2], bL[4][2];
            #pragma unroll
            for (int mt = 0; mt < 2; mt++) {
                uint32_t ad = bs + (wy * 32 + mt * 16 + (lane & 15)) * STR + s * 32 + (lane >> 4) * 16;
                LDM4(aH[mt], ad);
                if (NT == 3) LDM4(aL[mt], ad + OAL);
            }
            #pragma unroll
            for (int np = 0; np < 2; np++) {
                uint32_t bd = bs + OBH + (wx * 32 + np * 16 + (lane & 15)) * STR + s * 32 + (lane >> 4) * 16;
                uint32_t t0[4];
                LDM4(t0, bd);
                bH[2 * np][0] = t0[0]; bH[2 * np][1] = t0[2];
                bH[2 * np + 1][0] = t0[1]; bH[2 * np + 1][1] = t0[3];
                if (NT >= 2) {
                    uint32_t t1[4];
                    LDM4(t1, bd + (OBL - OBH));
                    bL[2 * np][0] = t1[0]; bL[2 * np][1] = t1[2];
                    bL[2 * np + 1][0] = t1[1]; bL[2 * np + 1][1] = t1[3];
                }
            }
            #pragma unroll
            for (int mt = 0; mt < 2; mt++)
                #pragma unroll
                for (int nt = 0; nt < 4; nt++)
                    MMA(acc[mt][nt], aH[mt], bH[nt][0], bH[nt][1]);
            if (NT >= 2) {
                #pragma unroll
                for (int mt = 0; mt < 2; mt++)
                    #pragma unroll
                    for (int nt = 0; nt < 4; nt++)
                        MMA(acc[mt][nt], aH[mt], bL[nt][0], bL[nt][1]);
            }
            if (NT == 3) {
                #pragma unroll
                for (int mt = 0; mt < 2; mt++)
                    #pragma unroll
                    for (int nt = 0; nt < 4; nt++)
                        MMA(acc[mt][nt], aL[mt], bH[nt][0], bH[nt][1]);
            }
        }
        __syncthreads();
    }

    float* cs = (float*)sm_ + wid * 1056;
    int g8 = lane >> 2, tg4 = lane & 3;
    #pragma unroll
    for (int mt = 0; mt < 2; mt++)
        #pragma unroll
        for (int nt = 0; nt < 4; nt++)
            #pragma unroll
            for (int ci = 0; ci < 4; ci++) {
                int r = mt * 16 + g8 + ((ci >> 1) & 1) * 8;
                int c = nt * 8 + tg4 * 2 + (ci & 1);
                cs[r * 33 + c] = acc[mt][nt][ci];
            }
    __syncwarp();
    int r0w = m0 + wy * 32, c0w = n0 + wx * 32;

    if constexpr (KIND == 0) {
        #pragma unroll
        for (int j = 0; j < 32; j++)
            Cf[(ll)bz * sC + (ll)(r0w + j) * ldc + c0w + lane] = cs[j * 33 + lane];
    }
    if constexpr (KIND == 1) {
        if (Xh) {
            int ldx = gridDim.x * 64;
            #pragma unroll
            for (int j = 0; j < 32; j++) {
                ll o = (ll)bz * sX + (ll)(r0w + j) * ldx + c0w + lane;
                float xv = __bfloat162float(Xh[o]) + __bfloat162float(Xl[o]);
                cs[j * 33 + lane] = c1 * xv + c2 * cs[j * 33 + lane];
            }
            __syncwarp();
        }
        if (Th) {
            int ldT = gridDim.y * 64;
            #pragma unroll
            for (int j = 0; j < 32; j++) {
                bf h, l; splitf(cs[lane * 33 + j], h, l);
                ll o = (ll)bz * sT + (ll)(c0w + j) * ldT + r0w + lane;
                Th[o] = h;
                if (Tl) Tl[o] = l;
            }
        }
        if (Oh) {
            int ldO = gridDim.x * 64;
            #pragma unroll
            for (int j = 0; j < 32; j++) {
                bf h, l; splitf(cs[j * 33 + lane], h, l);
                ll o = (ll)bz * sO + (ll)(r0w + j) * ldO + c0w + lane;
                Oh[o] = h;
                if (Ol) Ol[o] = l;
            }
        }
    }
    if constexpr (KIND == 3) {
        int part = c0w >> 9, hh = (c0w >> 6) & 7, d0 = c0w & 63;
        if (part == 2) {
            int b = r0w >> 12, nn = r0w & 4095;
            ll base = ((ll)(b * 8 + hh) * 64 + d0) * 4096 + nn + lane;
            #pragma unroll
            for (int j = 0; j < 32; j++) {
                bf h, l; splitf(cs[lane * 33 + j], h, l);
                g_vTh[base + (ll)j * 4096] = h;
                g_vTl[base + (ll)j * 4096] = l;
            }
        } else if (part == 1) {
            #pragma unroll
            for (int j = 0; j < 32; j++) {
                int rr = r0w + j, b = rr >> 12, nn = rr & 4095;
                bf h, l; splitf(cs[j * 33 + lane], h, l);
                ll o = ((ll)(b * 8 + hh) * 4096 + nn) * 64 + d0 + lane;
                g_kh[o] = h; g_klo[o] = l;
            }
        } else {
            #pragma unroll
            for (int j = 0; j < 32; j++) {
                int rr = r0w + j, b = rr >> 12, nn = rr & 4095;
                ll o = ((ll)(b * 8 + hh) * 4096 + nn) * 64 + d0 + lane;
                g_qh[o] = __float2bfloat16(cs[j * 33 + lane] * 0.125f);
            }
        }
    }
    if constexpr (KIND == 4) {
        float bv = bias[c0w + lane];
        #pragma unroll
        for (int j = 0; j < 32; j++) {
            ll o = (ll)(r0w + j) * ldc + c0w + lane;
            Cf[o] = cs[j * 33 + lane] + bv + Rf[o];
        }
    }
}

// ====== persistent fused Newton-Schulz (iters 0-4, 1-term bf16) ======
#define NS_OBH 9216
#define NS_SSTG 18432

__device__ __forceinline__ void gbar() {
    __threadfence();
    __syncthreads();
    if (threadIdx.x == 0) {
        unsigned gen = atomicAdd(&g_gen, 0u);
        if (atomicAdd(&g_cnt, 1u) == 511u) {
            atomicExch(&g_cnt, 0u);
            __threadfence();
            atomicAdd(&g_gen, 1u);
        } else {
            while (atomicAdd(&g_gen, 0u) == gen) __nanosleep(64);
        }
    }
    __syncthreads();
}

__device__ void nsg(unsigned char* sm_, uint32_t sb,
                    const bf* Ah, const bf* Bh,
                    bf* OAh, bf* OAl, bf* OTh, bf* OTl,
                    const bf* Xh, const bf* Xl, float c1, float c2,
                    int m0, int n0)
{
    int tid = threadIdx.x, wid = tid >> 5, lane = tid & 31;
    int wy = wid >> 1, wx = wid & 1;
    float acc[2][4][4] = {};
    int row8 = tid >> 3, c8 = tid & 7;
    auto loadStage = [&](int c, int stg) {
        int k0 = c << 6;
        uint32_t base = sb + stg * NS_SSTG;
        #pragma unroll
        for (int i = 0; i < 4; i++) {
            int r = row8 + i * 16;
            uint32_t so = r * STR + c8 * 16;
            CPA(base + so, Ah + (ll)(m0 + r) * 256 + k0 + c8 * 8);
            CPA(base + NS_OBH + so, Bh + (ll)(n0 + r) * 256 + k0 + c8 * 8);
        }
    };
    loadStage(0, 0);
    CPC();
    for (int c = 0; c < 4; c++) {
        if (c + 1 < 4) { loadStage(c + 1, (c + 1) & 1); CPC(); CPW(1); }
        else CPW(0);
        __syncthreads();
        uint32_t bs = sb + (c & 1) * NS_SSTG;
        #pragma unroll
        for (int s = 0; s < 4; s++) {
            uint32_t aH[2][4], bH[4][2];
            #pragma unroll
            for (int mt = 0; mt < 2; mt++) {
                uint32_t ad = bs + (wy * 32 + mt * 16 + (lane & 15)) * STR + s * 32 + (lane >> 4) * 16;
                LDM4(aH[mt], ad);
            }
            #pragma unroll
            for (int np = 0; np < 2; np++) {
                uint32_t bd = bs + NS_OBH + (wx * 32 + np * 16 + (lane & 15)) * STR + s * 32 + (lane >> 4) * 16;
                uint32_t t0[4];
                LDM4(t0, bd);
                bH[2 * np][0] = t0[0]; bH[2 * np][1] = t0[2];
                bH[2 * np + 1][0] = t0[1]; bH[2 * np + 1][1] = t0[3];
            }
            #pragma unroll
            for (int mt = 0; mt < 2; mt++)
                #pragma unroll
                for (int nt = 0; nt < 4; nt++)
                    MMA(acc[mt][nt], aH[mt], bH[nt][0], bH[nt][1]);
        }
        __syncthreads();
    }
    float* cs = (float*)sm_ + wid * 1056;
    int g8 = lane >> 2, tg4 = lane & 3;
    #pragma unroll
    for (int mt = 0; mt < 2; mt++)
        #pragma unroll
        for (int nt = 0; nt < 4; nt++)
            #pragma unroll
            for (int ci = 0; ci < 4; ci++) {
                int r = mt * 16 + g8 + ((ci >> 1) & 1) * 8;
                int c = nt * 8 + tg4 * 2 + (ci & 1);
                cs[r * 33 + c] = acc[mt][nt][ci];
            }
    __syncwarp();
    int r0w = m0 + wy * 32, c0w = n0 + wx * 32;
    if (Xh) {
        #pragma unroll
        for (int j = 0; j < 32; j++) {
            ll o = (ll)(r0w + j) * 256 + c0w + lane;
            float xv = ldcg_bf(Xh + o) + ldcg_bf(Xl + o);   // L1-bypass: persistent kernel
            cs[j * 33 + lane] = c1 * xv + c2 * cs[j * 33 + lane];
        }
        __syncwarp();
    }
    if (OTh) {
        #pragma unroll
        for (int j = 0; j < 32; j++) {
            bf h, l; splitf(cs[lane * 33 + j], h, l);
            ll o = (ll)(c0w + j) * 256 + r0w + lane;
            OTh[o] = h; OTl[o] = l;
        }
    }
    if (OAh) {
        #pragma unroll
        for (int j = 0; j < 32; j++) {
            bf h, l; splitf(cs[j * 33 + lane], h, l);
            ll o = (ll)(r0w + j) * 256 + c0w + lane;
            OAh[o] = h; OAl[o] = l;
        }
    }
}

__global__ __launch_bounds__(128, 4) void nsfused() {
    extern __shared__ __align__(16) unsigned char sm_[];
    uint32_t sb = smem_u32(sm_);
    int m0 = blockIdx.y * 64, n0 = blockIdx.x * 64;
    ll off = (ll)blockIdx.z * 65536;
    for (int it = 0; it < 5; it++) {
        int p = it & 1, q = 1 - p;
        nsg(sm_, sb, g_a2h + off, g_zTh + (ll)p * SQS + off,
            g_xzAh + off, g_xzAl + off, g_xzTh + off, g_xzTl + off,
            nullptr, nullptr, 0.f, 1.f, m0, n0);
        gbar();
        nsg(sm_, sb, g_xzAh + off, g_xzTh + off,
            nullptr, nullptr, g_m1Th + off, g_m1Tl + off,
            g_xzAh + off, g_xzAl + off, 7.f, -1.f, m0, n0);
        gbar();
        nsg(sm_, sb, g_xzAh + off, g_m1Th + off,
            nullptr, nullptr, g_m3Th + off, g_m3Tl + off,
            g_xzAh + off, g_xzAl + off, 15.f, -1.f, m0, n0);
        gbar();
        nsg(sm_, sb, g_zAh + (ll)p * SQS + off, g_m3Th + off,
            g_zAh + (ll)q * SQS + off, g_zAl + (ll)q * SQS + off,
            g_zTh + (ll)q * SQS + off, g_zTl + (ll)q * SQS + off,
            g_zAh + (ll)p * SQS + off, g_zAl + (ll)p * SQS + off, 3.25f, -0.25f, m0, n0);
        if (it < 4) gbar();
    }
}

// ---------------- small kernels ----------------
__global__ __launch_bounds__(256) void ln_k(const float* __restrict__ x,
                                            const float* __restrict__ w,
                                            const float* __restrict__ b) {
    ll base = (ll)blockIdx.x * 512;
    int t = threadIdx.x;
    float v0 = x[base + t], v1 = x[base + 256 + t];
    float mu = brs(v0 + v1) * (1.f / 512.f);
    float d0 = v0 - mu, d1 = v1 - mu;
    float var = brs(d0 * d0 + d1 * d1) * (1.f / 512.f);
    float r = rsqrtf(var + 1e-5f);
    g_xnh[base + t]       = __float2bfloat16(d0 * r * w[t] + b[t]);
    g_xnh[base + 256 + t] = __float2bfloat16(d1 * r * w[256 + t] + b[256 + t]);
}

__global__ void wtrans_k(const float* __restrict__ X, int R, int C, bf* Oh, bf* Ol) {
    __shared__ float t[32][33];
    int c0 = blockIdx.x * 32, r0 = blockIdx.y * 32, tx = threadIdx.x;
    for (int r = threadIdx.y; r < 32; r += 8) t[r][tx] = X[(ll)(r0 + r) * C + c0 + tx];
    __syncthreads();
    for (int r = threadIdx.y; r < 32; r += 8) {
        bf h, l; splitf(t[tx][r], h, l);
        ll o = (ll)(c0 + r) * R + r0 + tx;
        Oh[o] = h; Ol[o] = l;
    }
}

__global__ void landmark_k() {
    int m = blockIdx.x, bh = blockIdx.y, d = threadIdx.x;
    ll base = ((ll)bh * 4096 + m * 16) * 64 + d;
    float sq = 0.f, sk = 0.f;
    #pragma unroll
    for (int j = 0; j < 16; j++) {
        ll o = base + (ll)j * 64;
        sq += __bfloat162float(g_qh[o]);
        sk += __bfloat162float(g_kh[o]) + __bfloat162float(g_klo[o]);
    }
    ll o = ((ll)bh * 256 + m) * 64 + d;
    bf h, l;
    splitf(sq * 0.0625f, h, l); g_lqh[o] = h; g_lql[o] = l;
    splitf(sk * 0.0625f, h, l); g_lkh[o] = h; g_lkl[o] = l;
}

__global__ __launch_bounds__(256) void sm256a1_k() {
    ll base = (ll)blockIdx.x * 256;
    int t = threadIdx.x;
    float v = g_sf[base + t];
    float m = brm(v);
    float e = __expf(v - m);
    float s = brs(e);
    g_a1h[base + t] = __float2bfloat16(e / s);
}
__global__ __launch_bounds__(256) void sm256a2_k() {
    ll base = (ll)blockIdx.x * 256;
    int t = threadIdx.x;
    float v = g_a2f[base + t];
    float m = brm(v);
    float e = __expf(v - m);
    float s = brs(e);
    float r = e / s;
    g_a2f[base + t] = r;
    bf h, l; splitf(r, h, l);
    g_a2h[base + t] = h; g_a2l[base + t] = l;
}
__global__ __launch_bounds__(256) void sm4096_k() {
    ll base = (ll)blockIdx.x * 4096;
    int t = threadIdx.x;
    float v[16], m = -3.4e38f;
    #pragma unroll
    for (int i = 0; i < 16; i++) { v[i] = g_sf[base + t + i * 256]; m = fmaxf(m, v[i]); }
    m = brm(m);
    float s = 0.f;
    #pragma unroll
    for (int i = 0; i < 16; i++) { v[i] = __expf(v[i] - m); s += v[i]; }
    s = 1.f / brs(s);
    #pragma unroll
    for (int i = 0; i < 16; i++)
        g_a3h[base + t + i * 256] = __float2bfloat16(v[i] * s);
}

__global__ void reset_k() { g_redi[0] = 0; g_redi[1] = 0; }
__global__ __launch_bounds__(256) void rowsum_k() {
    const float* r = g_a2f + ((ll)blockIdx.x * 256 + threadIdx.x) * 256;
    float s = 0.f;
    for (int j = 0; j < 256; j++) s += r[j];
    s = brm(s);
    if (threadIdx.x == 0) atomicMax(&g_redi[0], __float_as_int(s));
}
__global__ __launch_bounds__(256) void colsum_k() {
    const float* b = g_a2f + (ll)blockIdx.x * 65536 + threadIdx.x;
    float s = 0.f;
    for (int i = 0; i < 256; i++) s += b[i * 256];
    s = brm(s);
    if (threadIdx.x == 0) atomicMax(&g_redi[1], __float_as_int(s));
}
__global__ void zinit_k() {
    __shared__ float t[32][33];
    int bh = blockIdx.z, i0 = blockIdx.y * 32, j0 = blockIdx.x * 32, tx = threadIdx.x;
    const float* a = g_a2f + (ll)bh * 65536;
    float sc = 1.f / (__int_as_float(g_redi[0]) * __int_as_float(g_redi[1]));
    for (int r = threadIdx.y; r < 32; r += 8) {
        float v = a[(ll)(i0 + r) * 256 + j0 + tx];
        t[r][tx] = v;
        bf h, l; splitf(v * sc, h, l);
        ll o = (ll)bh * 65536 + (ll)(i0 + r) * 256 + j0 + tx;
        g_zTh[o] = h; g_zTl[o] = l;
    }
    __syncthreads();
    for (int r = threadIdx.y; r < 32; r += 8) {
        bf h, l; splitf(t[tx][r] * sc, h, l);
        ll o = (ll)bh * 65536 + (ll)(j0 + r) * 256 + i0 + tx;
        g_zAh[o] = h; g_zAl[o] = l;
    }
}

// conv residual fused with gather+convert: ohh = gathered(ohA + conv(v)), hi only
__global__ __launch_bounds__(512) void conv_k(const float* __restrict__ wc) {
    __shared__ float sv[64][65];
    __shared__ float sw[33];
    int bh = blockIdx.y, h = bh & 7, n0 = blockIdx.x * 32;
    int tx = threadIdx.x, ty = threadIdx.y;
    int lt = ty * 64 + tx;
    if (lt < 33) sw[lt] = wc[h * 33 + lt];
    ll vb = (ll)bh * 262144;
    for (int dd = 0; dd < 8; dd++) {
        int d = dd * 8 + ty, n = n0 - 16 + tx;
        float v = 0.f;
        if (n >= 0 && n < 4096) {
            ll o = vb + (ll)d * 4096 + n;
            v = __bfloat162float(g_vTh[o]) + __bfloat162float(g_vTl[o]);
        }
        sv[d][tx] = v;
    }
    __syncthreads();
    ll rowb = (ll)((bh >> 3) * 4096 + n0) * 512 + h * 64 + tx;
    for (int k = 0; k < 4; k++) {
        int nl = ty * 4 + k;
        float acc = 0.f;
        #pragma unroll
        for (int t = 0; t < 33; t++) acc += sv[tx][nl + t] * sw[t];
        float o = g_ohA[vb + (ll)(n0 + nl) * 64 + tx] + acc;
        g_ohh[rowb + (ll)nl * 512] = __float2bfloat16(o);
    }
}

// ---------------- launch ----------------
#define GSA(p, s) cudaGetSymbolAddress((void**)&p, s)
#define NB (bf*)nullptr
#define NF (float*)nullptr
#define SM3 73728
#define SM2 55296
#define SMN 36864

extern "C" void kernel_launch(void* const* d_in, const int* in_sizes, int n_in,
                              void* d_out, int out_size) {
    const float* x = (const float*)d_in[0];
    const float* lnw = (const float*)d_in[1];
    const float* lnb = (const float*)d_in[2];
    const float* wqkv = (const float*)d_in[3];
    const float* wout = (const float*)d_in[4];
    const float* bout = (const float*)d_in[5];
    const float* wconv = (const float*)d_in[6];
    float* out = (float*)d_out;

    static bool init = false;
    static bf *xnh, *wqTh, *wqTl, *woTh, *woTl, *qh, *kh, *kl, *vTh, *vTl;
    static bf *lqh, *lql, *lkh, *lkl, *a1h, *a3h, *t1h;
    static bf *a2h, *a2l, *xzAh, *xzAl, *xzTh, *xzTl, *m1Th, *m1Tl, *m3Th, *m3Tl;
    static bf *zAh, *zAl, *zTh, *zTl, *avTh, *avTl, *ohh;
    static float *sf, *a2f, *ohA;
    if (!init) {
        init = true;
        GSA(xnh, g_xnh); GSA(wqTh, g_wqTh); GSA(wqTl, g_wqTl);
        GSA(woTh, g_woTh); GSA(woTl, g_woTl); GSA(qh, g_qh);
        GSA(kh, g_kh); GSA(kl, g_klo); GSA(vTh, g_vTh); GSA(vTl, g_vTl);
        GSA(lqh, g_lqh); GSA(lql, g_lql); GSA(lkh, g_lkh); GSA(lkl, g_lkl);
        GSA(a1h, g_a1h); GSA(a3h, g_a3h); GSA(t1h, g_t1h);
        GSA(a2h, g_a2h); GSA(a2l, g_a2l);
        GSA(xzAh, g_xzAh); GSA(xzAl, g_xzAl); GSA(xzTh, g_xzTh); GSA(xzTl, g_xzTl);
        GSA(m1Th, g_m1Th); GSA(m1Tl, g_m1Tl); GSA(m3Th, g_m3Th); GSA(m3Tl, g_m3Tl);
        GSA(zAh, g_zAh); GSA(zAl, g_zAl); GSA(zTh, g_zTh); GSA(zTl, g_zTl);
        GSA(avTh, g_avTh); GSA(avTl, g_avTl); GSA(ohh, g_ohh);
        GSA(sf, g_sf); GSA(a2f, g_a2f); GSA(ohA, g_ohA);
        cudaFuncSetAttribute(tg<3, 2>, cudaFuncAttributeMaxDynamicSharedMemorySize, SM2);
        cudaFuncSetAttribute(tg<0, 3>, cudaFuncAttributeMaxDynamicSharedMemorySize, SM3);
        cudaFuncSetAttribute(tg<1, 3>, cudaFuncAttributeMaxDynamicSharedMemorySize, SM3);
        cudaFuncSetAttribute(tg<1, 2>, cudaFuncAttributeMaxDynamicSharedMemorySize, SM2);
        cudaFuncSetAttribute(tg<0, 2>, cudaFuncAttributeMaxDynamicSharedMemorySize, SM2);
        cudaFuncSetAttribute(tg<4, 2>, cudaFuncAttributeMaxDynamicSharedMemorySize, SM2);
    }

    ln_k<<<16384, 256>>>(x, lnw, lnb);
    wtrans_k<<<dim3(48, 16), dim3(32, 8)>>>(wqkv, 512, 1536, wqTh, wqTl);
    wtrans_k<<<dim3(16, 16), dim3(32, 8)>>>(wout, 512, 512, woTh, woTl);
    // QKV projection (2-term) with scatter epilogue
    tg<3, 2><<<dim3(24, 256, 1), 128, SM2>>>(xnh, NB, 0, wqTh, wqTl, 0, 512,
        NF, 0, 0, NB, NB, 0, NB, NB, 0, NB, NB, 0, 0.f, 1.f, NF, NF);
    landmark_k<<<dim3(256, 32), 64>>>();
    // sim1 (2-term) -> fp32 -> softmax -> a1 (hi only)
    tg<0, 2><<<dim3(4, 64, 32), 128, SM2>>>(qh, NB, 262144, lkh, lkl, 16384, 64,
        sf, 1048576, 256, NB, NB, 0, NB, NB, 0, NB, NB, 0, 0.f, 1.f, NF, NF);
    sm256a1_k<<<131072, 256>>>();
    // sim2 (3-term, feeds pinv) -> fp32 -> softmax -> a2 hi/lo
    tg<0, 3><<<dim3(4, 4, 32), 128, SM3>>>(lqh, lql, 16384, lkh, lkl, 16384, 64,
        a2f, 65536, 256, NB, NB, 0, NB, NB, 0, NB, NB, 0, 0.f, 1.f, NF, NF);
    sm256a2_k<<<8192, 256>>>();
    // sim3 (2-term) -> fp32 -> softmax -> a3 (hi only)
    tg<0, 2><<<dim3(64, 4, 32), 128, SM2>>>(lqh, NB, 16384, kh, kl, 262144, 64,
        sf, 1048576, 4096, NB, NB, 0, NB, NB, 0, NB, NB, 0, 0.f, 1.f, NF, NF);
    sm4096_k<<<8192, 256>>>();
    reset_k<<<1, 1>>>();
    rowsum_k<<<32, 256>>>();
    colsum_k<<<32, 256>>>();
    zinit_k<<<dim3(8, 8, 32), dim3(32, 8)>>>();
    // Newton-Schulz iters 0-4: ONE persistent kernel with internal grid barriers.
    nsfused<<<dim3(4, 4, 32), 128, SMN>>>();
    // iter 5: full 3-term polish (p=1, q=0; final z lands in slot 0)
    {
        int p = 1, q2 = 0;
        tg<1, 3><<<dim3(4, 4, 32), 128, SM3>>>(a2h, a2l, 65536,
            zTh + p * SQS, zTl + p * SQS, 65536, 256,
            NF, 0, 0, xzAh, xzAl, 65536, xzTh, xzTl, 65536, NB, NB, 0, 0.f, 1.f, NF, NF);
        tg<1, 3><<<dim3(4, 4, 32), 128, SM3>>>(xzAh, xzAl, 65536, xzTh, xzTl, 65536, 256,
            NF, 0, 0, NB, NB, 0, m1Th, m1Tl, 65536, xzAh, xzAl, 65536, 7.f, -1.f, NF, NF);
        tg<1, 3><<<dim3(4, 4, 32), 128, SM3>>>(xzAh, xzAl, 65536, m1Th, m1Tl, 65536, 256,
            NF, 0, 0, NB, NB, 0, m3Th, m3Tl, 65536, xzAh, xzAl, 65536, 15.f, -1.f, NF, NF);
        tg<1, 3><<<dim3(4, 4, 32), 128, SM3>>>(zAh + p * SQS, zAl + p * SQS, 65536,
            m3Th, m3Tl, 65536, 256,
            NF, 0, 0, zAh + q2 * SQS, zAl + q2 * SQS, 65536,
            zTh + q2 * SQS, zTl + q2 * SQS, 65536,
            zAh + p * SQS, zAl + p * SQS, 65536, 3.25f, -0.25f, NF, NF);
    }
    // a3v^T = (a3 @ v)^T : 2-term
    tg<1, 2><<<dim3(1, 4, 32), 128, SM2>>>(a3h, NB, 1048576, vTh, vTl, 262144, 4096,
        NF, 0, 0, NB, NB, 0, avTh, avTl, 16384, NB, NB, 0, 0.f, 1.f, NF, NF);
    // t1 = a1 @ z : 2-term, hi-only out
    tg<1, 2><<<dim3(4, 64, 32), 128, SM2>>>(a1h, NB, 1048576, zTh, zTl, 65536, 256,
        NF, 0, 0, t1h, NB, 1048576, NB, NB, 0, NB, NB, 0, 0.f, 1.f, NF, NF);
    // oh = t1 @ a3v : 2-term, fp32 out
    tg<0, 2><<<dim3(1, 64, 32), 128, SM2>>>(t1h, NB, 1048576, avTh, avTl, 16384, 256,
        ohA, 262144, 64, NB, NB, 0, NB, NB, 0, NB, NB, 0, 0.f, 1.f, NF, NF);
    // conv residual + gather + convert (fused)
    conv_k<<<dim3(128, 32), dim3(64, 8)>>>(wconv);
    // out = oh @ wout + bias + x : 2-term
    tg<4, 2><<<dim3(8, 256, 1), 128, SM2>>>(ohh, NB, 0, woTh, woTl, 0, 512,
        out, 0, 512, NB, NB, 0, NB, NB, 0, NB, NB, 0, 0.f, 1.f, x, bout);
}

// round 13
// speedup vs baseline: 1.0404x; 1.0404x over previous
#include <cuda_runtime.h>
#include <cuda_bf16.h>
#include <cstdint>
typedef long long ll;
typedef __nv_bfloat16 bf;

#define QS  8388608ll
#define LS  524288ll
#define A1S 33554432ll
#define SQS 2097152ll
#define XNS 8388608ll

__device__ __forceinline__ uint32_t smem_u32(const void* p) {
    uint32_t a;
    asm("{ .reg .u64 t; cvta.to.shared.u64 t, %1; cvt.u32.u64 %0, t; }" : "=r"(a) : "l"(p));
    return a;
}
#define LDM4(r, a) asm volatile("ldmatrix.sync.aligned.m8n8.x4.shared.b16 {%0,%1,%2,%3}, [%4];" \
    : "=r"((r)[0]), "=r"((r)[1]), "=r"((r)[2]), "=r"((r)[3]) : "r"(a))
#define MMA(c, a, b0, b1) asm volatile( \
    "mma.sync.aligned.m16n8k16.row.col.f32.bf16.bf16.f32 " \
    "{%0,%1,%2,%3}, {%4,%5,%6,%7}, {%8,%9}, {%0,%1,%2,%3};" \
    : "+f"((c)[0]), "+f"((c)[1]), "+f"((c)[2]), "+f"((c)[3]) \
    : "r"((a)[0]), "r"((a)[1]), "r"((a)[2]), "r"((a)[3]), "r"(b0), "r"(b1))
#define CPA(d, s) asm volatile("cp.async.cg.shared.global [%0], [%1], 16;" :: "r"(d), "l"(s))
#define CPC() asm volatile("cp.async.commit_group;")
#define CPW(n) asm volatile("cp.async.wait_group %0;" :: "n"(n))

__device__ __forceinline__ void splitf(float v, bf& h, bf& l) {
    h = __float2bfloat16(v);
    l = __float2bfloat16(v - __bfloat162float(h));
}

// ---------- scratch ----------
__device__ bf g_xnh[XNS];
__device__ bf g_wqTh[786432], g_wqTl[786432], g_woTh[262144], g_woTl[262144];
__device__ bf g_qh[QS], g_kh[QS], g_klo[QS], g_vTh[QS], g_vTl[QS];
__device__ bf g_lqh[LS], g_lql[LS], g_lkh[LS], g_lkl[LS];
__device__ bf g_a1h[A1S], g_a3h[A1S], g_t1h[A1S];
__device__ float g_a2f[SQS];
__device__ bf g_a2h[SQS], g_a2l[SQS];
__device__ bf g_xzAh[SQS], g_xzAl[SQS], g_xzTh[SQS], g_xzTl[SQS];
__device__ bf g_m1Th[SQS], g_m1Tl[SQS], g_m3Th[SQS], g_m3Tl[SQS];
__device__ bf g_zAh[2 * SQS], g_zAl[2 * SQS], g_zTh[2 * SQS], g_zTl[2 * SQS];
__device__ bf g_avTh[LS], g_avTl[LS];
__device__ float g_ohA[QS];
__device__ bf g_ohh[XNS];
__device__ int g_redi[2];

// ---------- reductions ----------
__device__ __forceinline__ float wrs(float v) {
    #pragma unroll
    for (int o = 16; o; o >>= 1) v += __shfl_xor_sync(0xffffffffu, v, o);
    return v;
}
__device__ __forceinline__ float wrm(float v) {
    #pragma unroll
    for (int o = 16; o; o >>= 1) v = fmaxf(v, __shfl_xor_sync(0xffffffffu, v, o));
    return v;
}
__device__ __forceinline__ float brs(float v) {
    __shared__ float sm[32];
    int lane = threadIdx.x & 31, w = threadIdx.x >> 5;
    __syncthreads();
    v = wrs(v);
    if (!lane) sm[w] = v;
    __syncthreads();
    float r = (threadIdx.x < (blockDim.x >> 5)) ? sm[threadIdx.x] : 0.f;
    if (w == 0) { r = wrs(r); if (!lane) sm[0] = r; }
    __syncthreads();
    return sm[0];
}
__device__ __forceinline__ float brm(float v) {
    __shared__ float sm[32];
    int lane = threadIdx.x & 31, w = threadIdx.x >> 5;
    __syncthreads();
    v = wrm(v);
    if (!lane) sm[w] = v;
    __syncthreads();
    float r = (threadIdx.x < (blockDim.x >> 5)) ? sm[threadIdx.x] : -3.4e38f;
    if (w == 0) { r = wrm(r); if (!lane) sm[0] = r; }
    __syncthreads();
    return sm[0];
}

// ====== HMMA GEMM, cp.async double-buffered, term-major MMA order ======
// NT=1: Ah*Bh.  NT=2: Ah*Bh + Ah*Bl.  NT=3: + Al*Bh.
// KIND 0: fp32 C.  1: f = c1*X + c2*acc -> bf16 A-form (hi[,lo]) and/or T-form.
// 3: QKV scatter.  4: acc + bias + residual -> fp32.
#define STR 144
template<int KIND, int NT>
__global__ __launch_bounds__(128) void tg(
    const bf* __restrict__ Ah, const bf* __restrict__ Al, ll sA,
    const bf* __restrict__ Bh, const bf* __restrict__ Bl, ll sB, int K,
    float* __restrict__ Cf, ll sC, int ldc,
    bf* __restrict__ Oh, bf* __restrict__ Ol, ll sO,
    bf* __restrict__ Th, bf* __restrict__ Tl, ll sT,
    const bf* __restrict__ Xh, const bf* __restrict__ Xl, ll sX, float c1, float c2,
    const float* __restrict__ Rf, const float* __restrict__ bias)
{
    constexpr int NARR = (NT == 3) ? 4 : (NT == 2) ? 3 : 2;
    constexpr int SSTG = NARR * 64 * STR;
    constexpr int OAL = 64 * STR;
    constexpr int OBH = (NT == 3 ? 2 : 1) * 64 * STR;
    constexpr int OBL = OBH + 64 * STR;
    extern __shared__ __align__(16) unsigned char sm_[];
    uint32_t sb = smem_u32(sm_);
    int tid = threadIdx.x, wid = tid >> 5, lane = tid & 31;
    int wy = wid >> 1, wx = wid & 1;
    int m0 = blockIdx.y * 64, n0 = blockIdx.x * 64, bz = blockIdx.z;
    Ah += (ll)bz * sA;
    if (NT == 3) Al += (ll)bz * sA;
    Bh += (ll)bz * sB;
    if (NT >= 2) Bl += (ll)bz * sB;
    float acc[2][4][4] = {};
    int row8 = tid >> 3, c8 = tid & 7;
    int nch = K >> 6;

    auto loadStage = [&](int c, int stg) {
        int k0 = c << 6;
        uint32_t base = sb + stg * SSTG;
        #pragma unroll
        for (int i = 0; i < 4; i++) {
            int r = row8 + i * 16;
            uint32_t so = r * STR + c8 * 16;
            ll ga = (ll)(m0 + r) * K + k0 + c8 * 8;
            ll gb = (ll)(n0 + r) * K + k0 + c8 * 8;
            CPA(base + so, Ah + ga);
            CPA(base + OBH + so, Bh + gb);
            if (NT == 3) CPA(base + OAL + so, Al + ga);
            if (NT >= 2) CPA(base + OBL + so, Bl + gb);
        }
    };
    loadStage(0, 0);
    CPC();
    for (int c = 0; c < nch; c++) {
        if (c + 1 < nch) { loadStage(c + 1, (c + 1) & 1); CPC(); CPW(1); }
        else CPW(0);
        __syncthreads();
        uint32_t bs = sb + (c & 1) * SSTG;
        #pragma unroll
        for (int s = 0; s < 4; s++) {
            uint32_t aH[2][4], aL[2][4], bH[4][2], bL[4][2];
            #pragma unroll
            for (int mt = 0; mt < 2; mt++) {
                uint32_t ad = bs + (wy * 32 + mt * 16 + (lane & 15)) * STR + s * 32 + (lane >> 4) * 16;
                LDM4(aH[mt], ad);
                if (NT == 3) LDM4(aL[mt], ad + OAL);
            }
            #pragma unroll
            for (int np = 0; np < 2; np++) {
                uint32_t bd = bs + OBH + (wx * 32 + np * 16 + (lane & 15)) * STR + s * 32 + (lane >> 4) * 16;
                uint32_t t0[4];
                LDM4(t0, bd);
                bH[2 * np][0] = t0[0]; bH[2 * np][1] = t0[2];
                bH[2 * np + 1][0] = t0[1]; bH[2 * np + 1][1] = t0[3];
                if (NT >= 2) {
                    uint32_t t1[4];
                    LDM4(t1, bd + (OBL - OBH));
                    bL[2 * np][0] = t1[0]; bL[2 * np][1] = t1[2];
                    bL[2 * np + 1][0] = t1[1]; bL[2 * np + 1][1] = t1[3];
                }
            }
            #pragma unroll
            for (int mt = 0; mt < 2; mt++)
                #pragma unroll
                for (int nt = 0; nt < 4; nt++)
                    MMA(acc[mt][nt], aH[mt], bH[nt][0], bH[nt][1]);
            if (NT >= 2) {
                #pragma unroll
                for (int mt = 0; mt < 2; mt++)
                    #pragma unroll
                    for (int nt = 0; nt < 4; nt++)
                        MMA(acc[mt][nt], aH[mt], bL[nt][0], bL[nt][1]);
            }
            if (NT == 3) {
                #pragma unroll
                for (int mt = 0; mt < 2; mt++)
                    #pragma unroll
                    for (int nt = 0; nt < 4; nt++)
                        MMA(acc[mt][nt], aL[mt], bH[nt][0], bH[nt][1]);
            }
        }
        __syncthreads();
    }

    float* cs = (float*)sm_ + wid * 1056;
    int g8 = lane >> 2, tg4 = lane & 3;
    #pragma unroll
    for (int mt = 0; mt < 2; mt++)
        #pragma unroll
        for (int nt = 0; nt < 4; nt++)
            #pragma unroll
            for (int ci = 0; ci < 4; ci++) {
                int r = mt * 16 + g8 + ((ci >> 1) & 1) * 8;
                int c = nt * 8 + tg4 * 2 + (ci & 1);
                cs[r * 33 + c] = acc[mt][nt][ci];
            }
    __syncwarp();
    int r0w = m0 + wy * 32, c0w = n0 + wx * 32;

    if constexpr (KIND == 0) {
        #pragma unroll
        for (int j = 0; j < 32; j++)
            Cf[(ll)bz * sC + (ll)(r0w + j) * ldc + c0w + lane] = cs[j * 33 + lane];
    }
    if constexpr (KIND == 1) {
        if (Xh) {
            int ldx = gridDim.x * 64;
            #pragma unroll
            for (int j = 0; j < 32; j++) {
                ll o = (ll)bz * sX + (ll)(r0w + j) * ldx + c0w + lane;
                float xv = __bfloat162float(Xh[o]) + __bfloat162float(Xl[o]);
                cs[j * 33 + lane] = c1 * xv + c2 * cs[j * 33 + lane];
            }
            __syncwarp();
        }
        if (Th) {
            int ldT = gridDim.y * 64;
            #pragma unroll
            for (int j = 0; j < 32; j++) {
                bf h, l; splitf(cs[lane * 33 + j], h, l);
                ll o = (ll)bz * sT + (ll)(c0w + j) * ldT + r0w + lane;
                Th[o] = h;
                if (Tl) Tl[o] = l;
            }
        }
        if (Oh) {
            int ldO = gridDim.x * 64;
            #pragma unroll
            for (int j = 0; j < 32; j++) {
                bf h, l; splitf(cs[j * 33 + lane], h, l);
                ll o = (ll)bz * sO + (ll)(r0w + j) * ldO + c0w + lane;
                Oh[o] = h;
                if (Ol) Ol[o] = l;
            }
        }
    }
    if constexpr (KIND == 3) {
        int part = c0w >> 9, hh = (c0w >> 6) & 7, d0 = c0w & 63;
        if (part == 2) {
            int b = r0w >> 12, nn = r0w & 4095;
            ll base = ((ll)(b * 8 + hh) * 64 + d0) * 4096 + nn + lane;
            #pragma unroll
            for (int j = 0; j < 32; j++) {
                bf h, l; splitf(cs[lane * 33 + j], h, l);
                g_vTh[base + (ll)j * 4096] = h;
                g_vTl[base + (ll)j * 4096] = l;
            }
        } else if (part == 1) {
            #pragma unroll
            for (int j = 0; j < 32; j++) {
                int rr = r0w + j, b = rr >> 12, nn = rr & 4095;
                bf h, l; splitf(cs[j * 33 + lane], h, l);
                ll o = ((ll)(b * 8 + hh) * 4096 + nn) * 64 + d0 + lane;
                g_kh[o] = h; g_klo[o] = l;
            }
        } else {
            #pragma unroll
            for (int j = 0; j < 32; j++) {
                int rr = r0w + j, b = rr >> 12, nn = rr & 4095;
                ll o = ((ll)(b * 8 + hh) * 4096 + nn) * 64 + d0 + lane;
                g_qh[o] = __float2bfloat16(cs[j * 33 + lane] * 0.125f);
            }
        }
    }
    if constexpr (KIND == 4) {
        float bv = bias[c0w + lane];
        #pragma unroll
        for (int j = 0; j < 32; j++) {
            ll o = (ll)(r0w + j) * ldc + c0w + lane;
            Cf[o] = cs[j * 33 + lane] + bv + Rf[o];
        }
    }
}

// ---------------- small kernels ----------------
__global__ __launch_bounds__(256) void ln_k(const float* __restrict__ x,
                                            const float* __restrict__ w,
                                            const float* __restrict__ b) {
    ll base = (ll)blockIdx.x * 512;
    int t = threadIdx.x;
    float v0 = x[base + t], v1 = x[base + 256 + t];
    float mu = brs(v0 + v1) * (1.f / 512.f);
    float d0 = v0 - mu, d1 = v1 - mu;
    float var = brs(d0 * d0 + d1 * d1) * (1.f / 512.f);
    float r = rsqrtf(var + 1e-5f);
    g_xnh[base + t]       = __float2bfloat16(d0 * r * w[t] + b[t]);
    g_xnh[base + 256 + t] = __float2bfloat16(d1 * r * w[256 + t] + b[256 + t]);
}

__global__ void wtrans_k(const float* __restrict__ X, int R, int C, bf* Oh, bf* Ol) {
    __shared__ float t[32][33];
    int c0 = blockIdx.x * 32, r0 = blockIdx.y * 32, tx = threadIdx.x;
    for (int r = threadIdx.y; r < 32; r += 8) t[r][tx] = X[(ll)(r0 + r) * C + c0 + tx];
    __syncthreads();
    for (int r = threadIdx.y; r < 32; r += 8) {
        bf h, l; splitf(t[tx][r], h, l);
        ll o = (ll)(c0 + r) * R + r0 + tx;
        Oh[o] = h; Ol[o] = l;
    }
}

__global__ void landmark_k() {
    int m = blockIdx.x, bh = blockIdx.y, d = threadIdx.x;
    ll base = ((ll)bh * 4096 + m * 16) * 64 + d;
    float sq = 0.f, sk = 0.f;
    #pragma unroll
    for (int j = 0; j < 16; j++) {
        ll o = base + (ll)j * 64;
        sq += __bfloat162float(g_qh[o]);
        sk += __bfloat162float(g_kh[o]) + __bfloat162float(g_klo[o]);
    }
    ll o = ((ll)bh * 256 + m) * 64 + d;
    bf h, l;
    splitf(sq * 0.0625f, h, l); g_lqh[o] = h; g_lql[o] = l;
    splitf(sk * 0.0625f, h, l); g_lkh[o] = h; g_lkl[o] = l;
}

// in-place bf16 softmax over rows of 256 (a1h)
__global__ __launch_bounds__(256) void sm256a1_k() {
    ll base = (ll)blockIdx.x * 256;
    int t = threadIdx.x;
    float v = __bfloat162float(g_a1h[base + t]);
    float m = brm(v);
    float e = __expf(v - m);
    float s = brs(e);
    g_a1h[base + t] = __float2bfloat16(e / s);
}
__global__ __launch_bounds__(256) void sm256a2_k() {
    ll base = (ll)blockIdx.x * 256;
    int t = threadIdx.x;
    float v = g_a2f[base + t];
    float m = brm(v);
    float e = __expf(v - m);
    float s = brs(e);
    float r = e / s;
    g_a2f[base + t] = r;
    bf h, l; splitf(r, h, l);
    g_a2h[base + t] = h; g_a2l[base + t] = l;
}
// in-place bf16 softmax over rows of 4096 (a3h)
__global__ __launch_bounds__(256) void sm4096_k() {
    ll base = (ll)blockIdx.x * 4096;
    int t = threadIdx.x;
    float v[16], m = -3.4e38f;
    #pragma unroll
    for (int i = 0; i < 16; i++) {
        v[i] = __bfloat162float(g_a3h[base + t + i * 256]);
        m = fmaxf(m, v[i]);
    }
    m = brm(m);
    float s = 0.f;
    #pragma unroll
    for (int i = 0; i < 16; i++) { v[i] = __expf(v[i] - m); s += v[i]; }
    s = 1.f / brs(s);
    #pragma unroll
    for (int i = 0; i < 16; i++)
        g_a3h[base + t + i * 256] = __float2bfloat16(v[i] * s);
}

__global__ void reset_k() { g_redi[0] = 0; g_redi[1] = 0; }
__global__ __launch_bounds__(256) void rowsum_k() {
    const float* r = g_a2f + ((ll)blockIdx.x * 256 + threadIdx.x) * 256;
    float s = 0.f;
    for (int j = 0; j < 256; j++) s += r[j];
    s = brm(s);
    if (threadIdx.x == 0) atomicMax(&g_redi[0], __float_as_int(s));
}
__global__ __launch_bounds__(256) void colsum_k() {
    const float* b = g_a2f + (ll)blockIdx.x * 65536 + threadIdx.x;
    float s = 0.f;
    for (int i = 0; i < 256; i++) s += b[i * 256];
    s = brm(s);
    if (threadIdx.x == 0) atomicMax(&g_redi[1], __float_as_int(s));
}
__global__ void zinit_k() {
    __shared__ float t[32][33];
    int bh = blockIdx.z, i0 = blockIdx.y * 32, j0 = blockIdx.x * 32, tx = threadIdx.x;
    const float* a = g_a2f + (ll)bh * 65536;
    float sc = 1.f / (__int_as_float(g_redi[0]) * __int_as_float(g_redi[1]));
    for (int r = threadIdx.y; r < 32; r += 8) {
        float v = a[(ll)(i0 + r) * 256 + j0 + tx];
        t[r][tx] = v;
        bf h, l; splitf(v * sc, h, l);
        ll o = (ll)bh * 65536 + (ll)(i0 + r) * 256 + j0 + tx;
        g_zTh[o] = h; g_zTl[o] = l;
    }
    __syncthreads();
    for (int r = threadIdx.y; r < 32; r += 8) {
        bf h, l; splitf(t[tx][r] * sc, h, l);
        ll o = (ll)bh * 65536 + (ll)(j0 + r) * 256 + i0 + tx;
        g_zAh[o] = h; g_zAl[o] = l;
    }
}

// conv residual fused with gather+convert: ohh = gathered(ohA + conv(v)), hi only
__global__ __launch_bounds__(512) void conv_k(const float* __restrict__ wc) {
    __shared__ float sv[64][65];
    __shared__ float sw[33];
    int bh = blockIdx.y, h = bh & 7, n0 = blockIdx.x * 32;
    int tx = threadIdx.x, ty = threadIdx.y;
    int lt = ty * 64 + tx;
    if (lt < 33) sw[lt] = wc[h * 33 + lt];
    ll vb = (ll)bh * 262144;
    for (int dd = 0; dd < 8; dd++) {
        int d = dd * 8 + ty, n = n0 - 16 + tx;
        float v = 0.f;
        if (n >= 0 && n < 4096) {
            ll o = vb + (ll)d * 4096 + n;
            v = __bfloat162float(g_vTh[o]) + __bfloat162float(g_vTl[o]);
        }
        sv[d][tx] = v;
    }
    __syncthreads();
    ll rowb = (ll)((bh >> 3) * 4096 + n0) * 512 + h * 64 + tx;
    for (int k = 0; k < 4; k++) {
        int nl = ty * 4 + k;
        float acc = 0.f;
        #pragma unroll
        for (int t = 0; t < 33; t++) acc += sv[tx][nl + t] * sw[t];
        float o = g_ohA[vb + (ll)(n0 + nl) * 64 + tx] + acc;
        g_ohh[rowb + (ll)nl * 512] = __float2bfloat16(o);
    }
}

// ---------------- launch ----------------
#define GSA(p, s) cudaGetSymbolAddress((void**)&p, s)
#define NB (bf*)nullptr
#define NF (float*)nullptr
#define SM3 73728
#define SM2 55296
#define SM1 36864

extern "C" void kernel_launch(void* const* d_in, const int* in_sizes, int n_in,
                              void* d_out, int out_size) {
    const float* x = (const float*)d_in[0];
    const float* lnw = (const float*)d_in[1];
    const float* lnb = (const float*)d_in[2];
    const float* wqkv = (const float*)d_in[3];
    const float* wout = (const float*)d_in[4];
    const float* bout = (const float*)d_in[5];
    const float* wconv = (const float*)d_in[6];
    float* out = (float*)d_out;

    static bool init = false;
    static bf *xnh, *wqTh, *wqTl, *woTh, *woTl, *qh, *kh, *kl, *vTh, *vTl;
    static bf *lqh, *lql, *lkh, *lkl, *a1h, *a3h, *t1h;
    static bf *a2h, *a2l, *xzAh, *xzAl, *xzTh, *xzTl, *m1Th, *m1Tl, *m3Th, *m3Tl;
    static bf *zAh, *zAl, *zTh, *zTl, *avTh, *avTl, *ohh;
    static float *a2f, *ohA;
    if (!init) {
        init = true;
        GSA(xnh, g_xnh); GSA(wqTh, g_wqTh); GSA(wqTl, g_wqTl);
        GSA(woTh, g_woTh); GSA(woTl, g_woTl); GSA(qh, g_qh);
        GSA(kh, g_kh); GSA(kl, g_klo); GSA(vTh, g_vTh); GSA(vTl, g_vTl);
        GSA(lqh, g_lqh); GSA(lql, g_lql); GSA(lkh, g_lkh); GSA(lkl, g_lkl);
        GSA(a1h, g_a1h); GSA(a3h, g_a3h); GSA(t1h, g_t1h);
        GSA(a2h, g_a2h); GSA(a2l, g_a2l);
        GSA(xzAh, g_xzAh); GSA(xzAl, g_xzAl); GSA(xzTh, g_xzTh); GSA(xzTl, g_xzTl);
        GSA(m1Th, g_m1Th); GSA(m1Tl, g_m1Tl); GSA(m3Th, g_m3Th); GSA(m3Tl, g_m3Tl);
        GSA(zAh, g_zAh); GSA(zAl, g_zAl); GSA(zTh, g_zTh); GSA(zTl, g_zTl);
        GSA(avTh, g_avTh); GSA(avTl, g_avTl); GSA(ohh, g_ohh);
        GSA(a2f, g_a2f); GSA(ohA, g_ohA);
        cudaFuncSetAttribute(tg<3, 2>, cudaFuncAttributeMaxDynamicSharedMemorySize, SM2);
        cudaFuncSetAttribute(tg<0, 3>, cudaFuncAttributeMaxDynamicSharedMemorySize, SM3);
        cudaFuncSetAttribute(tg<1, 3>, cudaFuncAttributeMaxDynamicSharedMemorySize, SM3);
        cudaFuncSetAttribute(tg<1, 2>, cudaFuncAttributeMaxDynamicSharedMemorySize, SM2);
        cudaFuncSetAttribute(tg<0, 2>, cudaFuncAttributeMaxDynamicSharedMemorySize, SM2);
        cudaFuncSetAttribute(tg<1, 1>, cudaFuncAttributeMaxDynamicSharedMemorySize, SM1);
        cudaFuncSetAttribute(tg<4, 2>, cudaFuncAttributeMaxDynamicSharedMemorySize, SM2);
    }

    ln_k<<<16384, 256>>>(x, lnw, lnb);
    wtrans_k<<<dim3(48, 16), dim3(32, 8)>>>(wqkv, 512, 1536, wqTh, wqTl);
    wtrans_k<<<dim3(16, 16), dim3(32, 8)>>>(wout, 512, 512, woTh, woTl);
    // QKV projection (2-term) with scatter epilogue
    tg<3, 2><<<dim3(24, 256, 1), 128, SM2>>>(xnh, NB, 0, wqTh, wqTl, 0, 512,
        NF, 0, 0, NB, NB, 0, NB, NB, 0, NB, NB, 0, 0.f, 1.f, NF, NF);
    landmark_k<<<dim3(256, 32), 64>>>();
    // sim1 (2-term) -> bf16 logits in a1h -> in-place softmax
    tg<1, 2><<<dim3(4, 64, 32), 128, SM2>>>(qh, NB, 262144, lkh, lkl, 16384, 64,
        NF, 0, 0, a1h, NB, 1048576, NB, NB, 0, NB, NB, 0, 0.f, 1.f, NF, NF);
    sm256a1_k<<<131072, 256>>>();
    // sim2 (3-term, feeds pinv) -> fp32 -> softmax -> a2 hi/lo
    tg<0, 3><<<dim3(4, 4, 32), 128, SM3>>>(lqh, lql, 16384, lkh, lkl, 16384, 64,
        a2f, 65536, 256, NB, NB, 0, NB, NB, 0, NB, NB, 0, 0.f, 1.f, NF, NF);
    sm256a2_k<<<8192, 256>>>();
    // sim3 (2-term) -> bf16 logits in a3h -> in-place softmax
    tg<1, 2><<<dim3(64, 4, 32), 128, SM2>>>(lqh, NB, 16384, kh, kl, 262144, 64,
        NF, 0, 0, a3h, NB, 1048576, NB, NB, 0, NB, NB, 0, 0.f, 1.f, NF, NF);
    sm4096_k<<<8192, 256>>>();
    reset_k<<<1, 1>>>();
    rowsum_k<<<32, 256>>>();
    colsum_k<<<32, 256>>>();
    zinit_k<<<dim3(8, 8, 32), dim3(32, 8)>>>();
    // Newton-Schulz: iters 0-4 plain bf16 (launch loop — R10 proven), iter 5 3-term.
    for (int it = 0; it < 6; it++) {
        int p = it & 1, q2 = 1 - p;
        if (it < 5) {
            tg<1, 1><<<dim3(4, 4, 32), 128, SM1>>>(a2h, a2l, 65536,
                zTh + p * SQS, zTl + p * SQS, 65536, 256,
                NF, 0, 0, xzAh, xzAl, 65536, xzTh, xzTl, 65536, NB, NB, 0, 0.f, 1.f, NF, NF);
            tg<1, 1><<<dim3(4, 4, 32), 128, SM1>>>(xzAh, xzAl, 65536, xzTh, xzTl, 65536, 256,
                NF, 0, 0, NB, NB, 0, m1Th, m1Tl, 65536, xzAh, xzAl, 65536, 7.f, -1.f, NF, NF);
            tg<1, 1><<<dim3(4, 4, 32), 128, SM1>>>(xzAh, xzAl, 65536, m1Th, m1Tl, 65536, 256,
                NF, 0, 0, NB, NB, 0, m3Th, m3Tl, 65536, xzAh, xzAl, 65536, 15.f, -1.f, NF, NF);
            tg<1, 1><<<dim3(4, 4, 32), 128, SM1>>>(zAh + p * SQS, zAl + p * SQS, 65536,
                m3Th, m3Tl, 65536, 256,
                NF, 0, 0, zAh + q2 * SQS, zAl + q2 * SQS, 65536,
                zTh + q2 * SQS, zTl + q2 * SQS, 65536,
                zAh + p * SQS, zAl + p * SQS, 65536, 3.25f, -0.25f, NF, NF);
        } else {
            tg<1, 3><<<dim3(4, 4, 32), 128, SM3>>>(a2h, a2l, 65536,
                zTh + p * SQS, zTl + p * SQS, 65536, 256,
                NF, 0, 0, xzAh, xzAl, 65536, xzTh, xzTl, 65536, NB, NB, 0, 0.f, 1.f, NF, NF);
            tg<1, 3><<<dim3(4, 4, 32), 128, SM3>>>(xzAh, xzAl, 65536, xzTh, xzTl, 65536, 256,
                NF, 0, 0, NB, NB, 0, m1Th, m1Tl, 65536, xzAh, xzAl, 65536, 7.f, -1.f, NF, NF);
            tg<1, 3><<<dim3(4, 4, 32), 128, SM3>>>(xzAh, xzAl, 65536, m1Th, m1Tl, 65536, 256,
                NF, 0, 0, NB, NB, 0, m3Th, m3Tl, 65536, xzAh, xzAl, 65536, 15.f, -1.f, NF, NF);
            tg<1, 3><<<dim3(4, 4, 32), 128, SM3>>>(zAh + p * SQS, zAl + p * SQS, 65536,
                m3Th, m3Tl, 65536, 256,
                NF, 0, 0, zAh + q2 * SQS, zAl + q2 * SQS, 65536,
                zTh + q2 * SQS, zTl + q2 * SQS, 65536,
                zAh + p * SQS, zAl + p * SQS, 65536, 3.25f, -0.25f, NF, NF);
        }
    }
    // a3v^T = (a3 @ v)^T : 2-term
    tg<1, 2><<<dim3(1, 4, 32), 128, SM2>>>(a3h, NB, 1048576, vTh, vTl, 262144, 4096,
        NF, 0, 0, NB, NB, 0, avTh, avTl, 16384, NB, NB, 0, 0.f, 1.f, NF, NF);
    // t1 = a1 @ z : 2-term, hi-only out
    tg<1, 2><<<dim3(4, 64, 32), 128, SM2>>>(a1h, NB, 1048576, zTh, zTl, 65536, 256,
        NF, 0, 0, t1h, NB, 1048576, NB, NB, 0, NB, NB, 0, 0.f, 1.f, NF, NF);
    // oh = t1 @ a3v : 2-term, fp32 out
    tg<0, 2><<<dim3(1, 64, 32), 128, SM2>>>(t1h, NB, 1048576, avTh, avTl, 16384, 256,
        ohA, 262144, 64, NB, NB, 0, NB, NB, 0, NB, NB, 0, 0.f, 1.f, NF, NF);
    // conv residual + gather + convert (fused)
    conv_k<<<dim3(128, 32), dim3(64, 8)>>>(wconv);
    // out = oh @ wout + bias + x : 2-term
    tg<4, 2><<<dim3(8, 256, 1), 128, SM2>>>(ohh, NB, 0, woTh, woTl, 0, 512,
        out, 0, 512, NB, NB, 0, NB, NB, 0, NB, NB, 0, 0.f, 1.f, x, bout);
}

// round 14
// speedup vs baseline: 1.1557x; 1.1108x over previous
#include <cuda_runtime.h>
#include <cuda_bf16.h>
#include <cstdint>
typedef long long ll;
typedef __nv_bfloat16 bf;

#define QS  8388608ll
#define LS  524288ll
#define A1S 33554432ll
#define SQS 2097152ll
#define XNS 8388608ll

__device__ __forceinline__ uint32_t smem_u32(const void* p) {
    uint32_t a;
    asm("{ .reg .u64 t; cvta.to.shared.u64 t, %1; cvt.u32.u64 %0, t; }" : "=r"(a) : "l"(p));
    return a;
}
#define LDM4(r, a) asm volatile("ldmatrix.sync.aligned.m8n8.x4.shared.b16 {%0,%1,%2,%3}, [%4];" \
    : "=r"((r)[0]), "=r"((r)[1]), "=r"((r)[2]), "=r"((r)[3]) : "r"(a))
#define MMA(c, a, b0, b1) asm volatile( \
    "mma.sync.aligned.m16n8k16.row.col.f32.bf16.bf16.f32 " \
    "{%0,%1,%2,%3}, {%4,%5,%6,%7}, {%8,%9}, {%0,%1,%2,%3};" \
    : "+f"((c)[0]), "+f"((c)[1]), "+f"((c)[2]), "+f"((c)[3]) \
    : "r"((a)[0]), "r"((a)[1]), "r"((a)[2]), "r"((a)[3]), "r"(b0), "r"(b1))
#define CPA(d, s) asm volatile("cp.async.cg.shared.global [%0], [%1], 16;" :: "r"(d), "l"(s))
#define CPC() asm volatile("cp.async.commit_group;")
#define CPW(n) asm volatile("cp.async.wait_group %0;" :: "n"(n))

__device__ __forceinline__ void splitf(float v, bf& h, bf& l) {
    h = __float2bfloat16(v);
    l = __float2bfloat16(v - __bfloat162float(h));
}

// ---------- scratch ----------
__device__ bf g_xnh[XNS];
__device__ bf g_wqTh[786432], g_wqTl[786432], g_woTh[262144], g_woTl[262144];
__device__ bf g_qh[QS], g_kh[QS], g_klo[QS], g_vTh[QS], g_vTl[QS];
__device__ bf g_lqh[LS], g_lql[LS], g_lkh[LS], g_lkl[LS];
__device__ bf g_a1h[A1S], g_a3h[A1S];
__device__ float g_a2f[SQS];
__device__ bf g_a2h[SQS], g_a2l[SQS];
__device__ bf g_xzAh[SQS], g_xzAl[SQS], g_xzTh[SQS], g_xzTl[SQS];
__device__ bf g_m1Th[SQS], g_m1Tl[SQS], g_m3Th[SQS], g_m3Tl[SQS];
__device__ bf g_zAh[2 * SQS], g_zAl[2 * SQS], g_zTh[2 * SQS], g_zTl[2 * SQS];
__device__ bf g_avTh[LS], g_avTl[LS];
__device__ bf g_wTh[LS], g_wTl[LS];
__device__ float g_ohA[QS];
__device__ bf g_ohh[XNS];
__device__ int g_redi[2];

// ---------- reductions ----------
__device__ __forceinline__ float wrs(float v) {
    #pragma unroll
    for (int o = 16; o; o >>= 1) v += __shfl_xor_sync(0xffffffffu, v, o);
    return v;
}
__device__ __forceinline__ float wrm(float v) {
    #pragma unroll
    for (int o = 16; o; o >>= 1) v = fmaxf(v, __shfl_xor_sync(0xffffffffu, v, o));
    return v;
}
__device__ __forceinline__ float brs(float v) {
    __shared__ float sm[32];
    int lane = threadIdx.x & 31, w = threadIdx.x >> 5;
    __syncthreads();
    v = wrs(v);
    if (!lane) sm[w] = v;
    __syncthreads();
    float r = (threadIdx.x < (blockDim.x >> 5)) ? sm[threadIdx.x] : 0.f;
    if (w == 0) { r = wrs(r); if (!lane) sm[0] = r; }
    __syncthreads();
    return sm[0];
}
__device__ __forceinline__ float brm(float v) {
    __shared__ float sm[32];
    int lane = threadIdx.x & 31, w = threadIdx.x >> 5;
    __syncthreads();
    v = wrm(v);
    if (!lane) sm[w] = v;
    __syncthreads();
    float r = (threadIdx.x < (blockDim.x >> 5)) ? sm[threadIdx.x] : -3.4e38f;
    if (w == 0) { r = wrm(r); if (!lane) sm[0] = r; }
    __syncthreads();
    return sm[0];
}

// ====== HMMA GEMM, cp.async double-buffered, term-major MMA order ======
// NT=1: Ah*Bh.  NT=2: Ah*Bh + Ah*Bl.  NT=3: + Al*Bh.
// KIND 0: fp32 C.  1: f = c1*X + c2*acc -> bf16 A-form (hi[,lo]) and/or T-form.
// 3: QKV scatter.  4: acc + bias + residual -> fp32.
#define STR 144
template<int KIND, int NT>
__global__ __launch_bounds__(128) void tg(
    const bf* __restrict__ Ah, const bf* __restrict__ Al, ll sA,
    const bf* __restrict__ Bh, const bf* __restrict__ Bl, ll sB, int K,
    float* __restrict__ Cf, ll sC, int ldc,
    bf* __restrict__ Oh, bf* __restrict__ Ol, ll sO,
    bf* __restrict__ Th, bf* __restrict__ Tl, ll sT,
    const bf* __restrict__ Xh, const bf* __restrict__ Xl, ll sX, float c1, float c2,
    const float* __restrict__ Rf, const float* __restrict__ bias)
{
    constexpr int NARR = (NT == 3) ? 4 : (NT == 2) ? 3 : 2;
    constexpr int SSTG = NARR * 64 * STR;
    constexpr int OAL = 64 * STR;
    constexpr int OBH = (NT == 3 ? 2 : 1) * 64 * STR;
    constexpr int OBL = OBH + 64 * STR;
    extern __shared__ __align__(16) unsigned char sm_[];
    uint32_t sb = smem_u32(sm_);
    int tid = threadIdx.x, wid = tid >> 5, lane = tid & 31;
    int wy = wid >> 1, wx = wid & 1;
    int m0 = blockIdx.y * 64, n0 = blockIdx.x * 64, bz = blockIdx.z;
    Ah += (ll)bz * sA;
    if (NT == 3) Al += (ll)bz * sA;
    Bh += (ll)bz * sB;
    if (NT >= 2) Bl += (ll)bz * sB;
    float acc[2][4][4] = {};
    int row8 = tid >> 3, c8 = tid & 7;
    int nch = K >> 6;

    auto loadStage = [&](int c, int stg) {
        int k0 = c << 6;
        uint32_t base = sb + stg * SSTG;
        #pragma unroll
        for (int i = 0; i < 4; i++) {
            int r = row8 + i * 16;
            uint32_t so = r * STR + c8 * 16;
            ll ga = (ll)(m0 + r) * K + k0 + c8 * 8;
            ll gb = (ll)(n0 + r) * K + k0 + c8 * 8;
            CPA(base + so, Ah + ga);
            CPA(base + OBH + so, Bh + gb);
            if (NT == 3) CPA(base + OAL + so, Al + ga);
            if (NT >= 2) CPA(base + OBL + so, Bl + gb);
        }
    };
    loadStage(0, 0);
    CPC();
    for (int c = 0; c < nch; c++) {
        if (c + 1 < nch) { loadStage(c + 1, (c + 1) & 1); CPC(); CPW(1); }
        else CPW(0);
        __syncthreads();
        uint32_t bs = sb + (c & 1) * SSTG;
        #pragma unroll
        for (int s = 0; s < 4; s++) {
            uint32_t aH[2][4], aL[2][4], bH[4][2], bL[4][2];
            #pragma unroll
            for (int mt = 0; mt < 2; mt++) {
                uint32_t ad = bs + (wy * 32 + mt * 16 + (lane & 15)) * STR + s * 32 + (lane >> 4) * 16;
                LDM4(aH[mt], ad);
                if (NT == 3) LDM4(aL[mt], ad + OAL);
            }
            #pragma unroll
            for (int np = 0; np < 2; np++) {
                uint32_t bd = bs + OBH + (wx * 32 + np * 16 + (lane & 15)) * STR + s * 32 + (lane >> 4) * 16;
                uint32_t t0[4];
                LDM4(t0, bd);
                bH[2 * np][0] = t0[0]; bH[2 * np][1] = t0[2];
                bH[2 * np + 1][0] = t0[1]; bH[2 * np + 1][1] = t0[3];
                if (NT >= 2) {
                    uint32_t t1[4];
                    LDM4(t1, bd + (OBL - OBH));
                    bL[2 * np][0] = t1[0]; bL[2 * np][1] = t1[2];
                    bL[2 * np + 1][0] = t1[1]; bL[2 * np + 1][1] = t1[3];
                }
            }
            #pragma unroll
            for (int mt = 0; mt < 2; mt++)
                #pragma unroll
                for (int nt = 0; nt < 4; nt++)
                    MMA(acc[mt][nt], aH[mt], bH[nt][0], bH[nt][1]);
            if (NT >= 2) {
                #pragma unroll
                for (int mt = 0; mt < 2; mt++)
                    #pragma unroll
                    for (int nt = 0; nt < 4; nt++)
                        MMA(acc[mt][nt], aH[mt], bL[nt][0], bL[nt][1]);
            }
            if (NT == 3) {
                #pragma unroll
                for (int mt = 0; mt < 2; mt++)
                    #pragma unroll
                    for (int nt = 0; nt < 4; nt++)
                        MMA(acc[mt][nt], aL[mt], bH[nt][0], bH[nt][1]);
            }
        }
        __syncthreads();
    }

    float* cs = (float*)sm_ + wid * 1056;
    int g8 = lane >> 2, tg4 = lane & 3;
    #pragma unroll
    for (int mt = 0; mt < 2; mt++)
        #pragma unroll
        for (int nt = 0; nt < 4; nt++)
            #pragma unroll
            for (int ci = 0; ci < 4; ci++) {
                int r = mt * 16 + g8 + ((ci >> 1) & 1) * 8;
                int c = nt * 8 + tg4 * 2 + (ci & 1);
                cs[r * 33 + c] = acc[mt][nt][ci];
            }
    __syncwarp();
    int r0w = m0 + wy * 32, c0w = n0 + wx * 32;

    if constexpr (KIND == 0) {
        #pragma unroll
        for (int j = 0; j < 32; j++)
            Cf[(ll)bz * sC + (ll)(r0w + j) * ldc + c0w + lane] = cs[j * 33 + lane];
    }
    if constexpr (KIND == 1) {
        if (Xh) {
            int ldx = gridDim.x * 64;
            #pragma unroll
            for (int j = 0; j < 32; j++) {
                ll o = (ll)bz * sX + (ll)(r0w + j) * ldx + c0w + lane;
                float xv = __bfloat162float(Xh[o]) + __bfloat162float(Xl[o]);
                cs[j * 33 + lane] = c1 * xv + c2 * cs[j * 33 + lane];
            }
            __syncwarp();
        }
        if (Th) {
            int ldT = gridDim.y * 64;
            #pragma unroll
            for (int j = 0; j < 32; j++) {
                bf h, l; splitf(cs[lane * 33 + j], h, l);
                ll o = (ll)bz * sT + (ll)(c0w + j) * ldT + r0w + lane;
                Th[o] = h;
                if (Tl) Tl[o] = l;
            }
        }
        if (Oh) {
            int ldO = gridDim.x * 64;
            #pragma unroll
            for (int j = 0; j < 32; j++) {
                bf h, l; splitf(cs[j * 33 + lane], h, l);
                ll o = (ll)bz * sO + (ll)(r0w + j) * ldO + c0w + lane;
                Oh[o] = h;
                if (Ol) Ol[o] = l;
            }
        }
    }
    if constexpr (KIND == 3) {
        int part = c0w >> 9, hh = (c0w >> 6) & 7, d0 = c0w & 63;
        if (part == 2) {
            int b = r0w >> 12, nn = r0w & 4095;
            ll base = ((ll)(b * 8 + hh) * 64 + d0) * 4096 + nn + lane;
            #pragma unroll
            for (int j = 0; j < 32; j++) {
                bf h, l; splitf(cs[lane * 33 + j], h, l);
                g_vTh[base + (ll)j * 4096] = h;
                g_vTl[base + (ll)j * 4096] = l;
            }
        } else if (part == 1) {
            #pragma unroll
            for (int j = 0; j < 32; j++) {
                int rr = r0w + j, b = rr >> 12, nn = rr & 4095;
                bf h, l; splitf(cs[j * 33 + lane], h, l);
                ll o = ((ll)(b * 8 + hh) * 4096 + nn) * 64 + d0 + lane;
                g_kh[o] = h; g_klo[o] = l;
            }
        } else {
            #pragma unroll
            for (int j = 0; j < 32; j++) {
                int rr = r0w + j, b = rr >> 12, nn = rr & 4095;
                ll o = ((ll)(b * 8 + hh) * 4096 + nn) * 64 + d0 + lane;
                g_qh[o] = __float2bfloat16(cs[j * 33 + lane] * 0.125f);
            }
        }
    }
    if constexpr (KIND == 4) {
        float bv = bias[c0w + lane];
        #pragma unroll
        for (int j = 0; j < 32; j++) {
            ll o = (ll)(r0w + j) * ldc + c0w + lane;
            Cf[o] = cs[j * 33 + lane] + bv + Rf[o];
        }
    }
}

// ---------------- small kernels ----------------
__global__ __launch_bounds__(256) void ln_k(const float* __restrict__ x,
                                            const float* __restrict__ w,
                                            const float* __restrict__ b) {
    ll base = (ll)blockIdx.x * 512;
    int t = threadIdx.x;
    float v0 = x[base + t], v1 = x[base + 256 + t];
    float mu = brs(v0 + v1) * (1.f / 512.f);
    float d0 = v0 - mu, d1 = v1 - mu;
    float var = brs(d0 * d0 + d1 * d1) * (1.f / 512.f);
    float r = rsqrtf(var + 1e-5f);
    g_xnh[base + t]       = __float2bfloat16(d0 * r * w[t] + b[t]);
    g_xnh[base + 256 + t] = __float2bfloat16(d1 * r * w[256 + t] + b[256 + t]);
}

__global__ void wtrans_k(const float* __restrict__ X, int R, int C, bf* Oh, bf* Ol) {
    __shared__ float t[32][33];
    int c0 = blockIdx.x * 32, r0 = blockIdx.y * 32, tx = threadIdx.x;
    for (int r = threadIdx.y; r < 32; r += 8) t[r][tx] = X[(ll)(r0 + r) * C + c0 + tx];
    __syncthreads();
    for (int r = threadIdx.y; r < 32; r += 8) {
        bf h, l; splitf(t[tx][r], h, l);
        ll o = (ll)(c0 + r) * R + r0 + tx;
        Oh[o] = h; Ol[o] = l;
    }
}

__global__ void landmark_k() {
    int m = blockIdx.x, bh = blockIdx.y, d = threadIdx.x;
    ll base = ((ll)bh * 4096 + m * 16) * 64 + d;
    float sq = 0.f, sk = 0.f;
    #pragma unroll
    for (int j = 0; j < 16; j++) {
        ll o = base + (ll)j * 64;
        sq += __bfloat162float(g_qh[o]);
        sk += __bfloat162float(g_kh[o]) + __bfloat162float(g_klo[o]);
    }
    ll o = ((ll)bh * 256 + m) * 64 + d;
    bf h, l;
    splitf(sq * 0.0625f, h, l); g_lqh[o] = h; g_lql[o] = l;
    splitf(sk * 0.0625f, h, l); g_lkh[o] = h; g_lkl[o] = l;
}

// in-place bf16 softmax over rows of 256 (a1h)
__global__ __launch_bounds__(256) void sm256a1_k() {
    ll base = (ll)blockIdx.x * 256;
    int t = threadIdx.x;
    float v = __bfloat162float(g_a1h[base + t]);
    float m = brm(v);
    float e = __expf(v - m);
    float s = brs(e);
    g_a1h[base + t] = __float2bfloat16(e / s);
}
__global__ __launch_bounds__(256) void sm256a2_k() {
    ll base = (ll)blockIdx.x * 256;
    int t = threadIdx.x;
    float v = g_a2f[base + t];
    float m = brm(v);
    float e = __expf(v - m);
    float s = brs(e);
    float r = e / s;
    g_a2f[base + t] = r;
    bf h, l; splitf(r, h, l);
    g_a2h[base + t] = h; g_a2l[base + t] = l;
}
// in-place bf16 softmax over rows of 4096 (a3h)
__global__ __launch_bounds__(256) void sm4096_k() {
    ll base = (ll)blockIdx.x * 4096;
    int t = threadIdx.x;
    float v[16], m = -3.4e38f;
    #pragma unroll
    for (int i = 0; i < 16; i++) {
        v[i] = __bfloat162float(g_a3h[base + t + i * 256]);
        m = fmaxf(m, v[i]);
    }
    m = brm(m);
    float s = 0.f;
    #pragma unroll
    for (int i = 0; i < 16; i++) { v[i] = __expf(v[i] - m); s += v[i]; }
    s = 1.f / brs(s);
    #pragma unroll
    for (int i = 0; i < 16; i++)
        g_a3h[base + t + i * 256] = __float2bfloat16(v[i] * s);
}

__global__ void reset_k() { g_redi[0] = 0; g_redi[1] = 0; }
__global__ __launch_bounds__(256) void rowsum_k() {
    const float* r = g_a2f + ((ll)blockIdx.x * 256 + threadIdx.x) * 256;
    float s = 0.f;
    for (int j = 0; j < 256; j++) s += r[j];
    s = brm(s);
    if (threadIdx.x == 0) atomicMax(&g_redi[0], __float_as_int(s));
}
__global__ __launch_bounds__(256) void colsum_k() {
    const float* b = g_a2f + (ll)blockIdx.x * 65536 + threadIdx.x;
    float s = 0.f;
    for (int i = 0; i < 256; i++) s += b[i * 256];
    s = brm(s);
    if (threadIdx.x == 0) atomicMax(&g_redi[1], __float_as_int(s));
}
__global__ void zinit_k() {
    __shared__ float t[32][33];
    int bh = blockIdx.z, i0 = blockIdx.y * 32, j0 = blockIdx.x * 32, tx = threadIdx.x;
    const float* a = g_a2f + (ll)bh * 65536;
    float sc = 1.f / (__int_as_float(g_redi[0]) * __int_as_float(g_redi[1]));
    for (int r = threadIdx.y; r < 32; r += 8) {
        float v = a[(ll)(i0 + r) * 256 + j0 + tx];
        t[r][tx] = v;
        bf h, l; splitf(v * sc, h, l);
        ll o = (ll)bh * 65536 + (ll)(i0 + r) * 256 + j0 + tx;
        g_zTh[o] = h; g_zTl[o] = l;
    }
    __syncthreads();
    for (int r = threadIdx.y; r < 32; r += 8) {
        bf h, l; splitf(t[tx][r] * sc, h, l);
        ll o = (ll)bh * 65536 + (ll)(j0 + r) * 256 + i0 + tx;
        g_zAh[o] = h; g_zAl[o] = l;
    }
}

// conv residual fused with gather+convert: ohh = gathered(ohA + conv(v)), hi only
__global__ __launch_bounds__(512) void conv_k(const float* __restrict__ wc) {
    __shared__ float sv[64][65];
    __shared__ float sw[33];
    int bh = blockIdx.y, h = bh & 7, n0 = blockIdx.x * 32;
    int tx = threadIdx.x, ty = threadIdx.y;
    int lt = ty * 64 + tx;
    if (lt < 33) sw[lt] = wc[h * 33 + lt];
    ll vb = (ll)bh * 262144;
    for (int dd = 0; dd < 8; dd++) {
        int d = dd * 8 + ty, n = n0 - 16 + tx;
        float v = 0.f;
        if (n >= 0 && n < 4096) {
            ll o = vb + (ll)d * 4096 + n;
            v = __bfloat162float(g_vTh[o]) + __bfloat162float(g_vTl[o]);
        }
        sv[d][tx] = v;
    }
    __syncthreads();
    ll rowb = (ll)((bh >> 3) * 4096 + n0) * 512 + h * 64 + tx;
    for (int k = 0; k < 4; k++) {
        int nl = ty * 4 + k;
        float acc = 0.f;
        #pragma unroll
        for (int t = 0; t < 33; t++) acc += sv[tx][nl + t] * sw[t];
        float o = g_ohA[vb + (ll)(n0 + nl) * 64 + tx] + acc;
        g_ohh[rowb + (ll)nl * 512] = __float2bfloat16(o);
    }
}

// ---------------- launch ----------------
#define GSA(p, s) cudaGetSymbolAddress((void**)&p, s)
#define NB (bf*)nullptr
#define NF (float*)nullptr
#define SM3 73728
#define SM2 55296
#define SM1 36864

extern "C" void kernel_launch(void* const* d_in, const int* in_sizes, int n_in,
                              void* d_out, int out_size) {
    const float* x = (const float*)d_in[0];
    const float* lnw = (const float*)d_in[1];
    const float* lnb = (const float*)d_in[2];
    const float* wqkv = (const float*)d_in[3];
    const float* wout = (const float*)d_in[4];
    const float* bout = (const float*)d_in[5];
    const float* wconv = (const float*)d_in[6];
    float* out = (float*)d_out;

    static bool init = false;
    static bf *xnh, *wqTh, *wqTl, *woTh, *woTl, *qh, *kh, *kl, *vTh, *vTl;
    static bf *lqh, *lql, *lkh, *lkl, *a1h, *a3h;
    static bf *a2h, *a2l, *xzAh, *xzAl, *xzTh, *xzTl, *m1Th, *m1Tl, *m3Th, *m3Tl;
    static bf *zAh, *zAl, *zTh, *zTl, *avTh, *avTl, *wTh, *wTl, *ohh;
    static float *a2f, *ohA;
    if (!init) {
        init = true;
        GSA(xnh, g_xnh); GSA(wqTh, g_wqTh); GSA(wqTl, g_wqTl);
        GSA(woTh, g_woTh); GSA(woTl, g_woTl); GSA(qh, g_qh);
        GSA(kh, g_kh); GSA(kl, g_klo); GSA(vTh, g_vTh); GSA(vTl, g_vTl);
        GSA(lqh, g_lqh); GSA(lql, g_lql); GSA(lkh, g_lkh); GSA(lkl, g_lkl);
        GSA(a1h, g_a1h); GSA(a3h, g_a3h);
        GSA(a2h, g_a2h); GSA(a2l, g_a2l);
        GSA(xzAh, g_xzAh); GSA(xzAl, g_xzAl); GSA(xzTh, g_xzTh); GSA(xzTl, g_xzTl);
        GSA(m1Th, g_m1Th); GSA(m1Tl, g_m1Tl); GSA(m3Th, g_m3Th); GSA(m3Tl, g_m3Tl);
        GSA(zAh, g_zAh); GSA(zAl, g_zAl); GSA(zTh, g_zTh); GSA(zTl, g_zTl);
        GSA(avTh, g_avTh); GSA(avTl, g_avTl); GSA(wTh, g_wTh); GSA(wTl, g_wTl);
        GSA(ohh, g_ohh);
        GSA(a2f, g_a2f); GSA(ohA, g_ohA);
        cudaFuncSetAttribute(tg<3, 2>, cudaFuncAttributeMaxDynamicSharedMemorySize, SM2);
        cudaFuncSetAttribute(tg<0, 3>, cudaFuncAttributeMaxDynamicSharedMemorySize, SM3);
        cudaFuncSetAttribute(tg<1, 3>, cudaFuncAttributeMaxDynamicSharedMemorySize, SM3);
        cudaFuncSetAttribute(tg<1, 2>, cudaFuncAttributeMaxDynamicSharedMemorySize, SM2);
        cudaFuncSetAttribute(tg<0, 2>, cudaFuncAttributeMaxDynamicSharedMemorySize, SM2);
        cudaFuncSetAttribute(tg<1, 1>, cudaFuncAttributeMaxDynamicSharedMemorySize, SM1);
        cudaFuncSetAttribute(tg<4, 2>, cudaFuncAttributeMaxDynamicSharedMemorySize, SM2);
    }

    ln_k<<<16384, 256>>>(x, lnw, lnb);
    wtrans_k<<<dim3(48, 16), dim3(32, 8)>>>(wqkv, 512, 1536, wqTh, wqTl);
    wtrans_k<<<dim3(16, 16), dim3(32, 8)>>>(wout, 512, 512, woTh, woTl);
    // QKV projection (2-term) with scatter epilogue
    tg<3, 2><<<dim3(24, 256, 1), 128, SM2>>>(xnh, NB, 0, wqTh, wqTl, 0, 512,
        NF, 0, 0, NB, NB, 0, NB, NB, 0, NB, NB, 0, 0.f, 1.f, NF, NF);
    landmark_k<<<dim3(256, 32), 64>>>();
    // sim1 (2-term) -> bf16 logits in a1h -> in-place softmax
    tg<1, 2><<<dim3(4, 64, 32), 128, SM2>>>(qh, NB, 262144, lkh, lkl, 16384, 64,
        NF, 0, 0, a1h, NB, 1048576, NB, NB, 0, NB, NB, 0, 0.f, 1.f, NF, NF);
    sm256a1_k<<<131072, 256>>>();
    // sim2 (3-term, feeds pinv) -> fp32 -> softmax -> a2 hi/lo
    tg<0, 3><<<dim3(4, 4, 32), 128, SM3>>>(lqh, lql, 16384, lkh, lkl, 16384, 64,
        a2f, 65536, 256, NB, NB, 0, NB, NB, 0, NB, NB, 0, 0.f, 1.f, NF, NF);
    sm256a2_k<<<8192, 256>>>();
    // sim3 (2-term) -> bf16 logits in a3h -> in-place softmax
    tg<1, 2><<<dim3(64, 4, 32), 128, SM2>>>(lqh, NB, 16384, kh, kl, 262144, 64,
        NF, 0, 0, a3h, NB, 1048576, NB, NB, 0, NB, NB, 0, 0.f, 1.f, NF, NF);
    sm4096_k<<<8192, 256>>>();
    reset_k<<<1, 1>>>();
    rowsum_k<<<32, 256>>>();
    colsum_k<<<32, 256>>>();
    zinit_k<<<dim3(8, 8, 32), dim3(32, 8)>>>();
    // Newton-Schulz: iters 0-4 plain bf16, iter 5 3-term. Final z in slot 0.
    for (int it = 0; it < 6; it++) {
        int p = it & 1, q2 = 1 - p;
        if (it < 5) {
            tg<1, 1><<<dim3(4, 4, 32), 128, SM1>>>(a2h, a2l, 65536,
                zTh + p * SQS, zTl + p * SQS, 65536, 256,
                NF, 0, 0, xzAh, xzAl, 65536, xzTh, xzTl, 65536, NB, NB, 0, 0.f, 1.f, NF, NF);
            tg<1, 1><<<dim3(4, 4, 32), 128, SM1>>>(xzAh, xzAl, 65536, xzTh, xzTl, 65536, 256,
                NF, 0, 0, NB, NB, 0, m1Th, m1Tl, 65536, xzAh, xzAl, 65536, 7.f, -1.f, NF, NF);
            tg<1, 1><<<dim3(4, 4, 32), 128, SM1>>>(xzAh, xzAl, 65536, m1Th, m1Tl, 65536, 256,
                NF, 0, 0, NB, NB, 0, m3Th, m3Tl, 65536, xzAh, xzAl, 65536, 15.f, -1.f, NF, NF);
            tg<1, 1><<<dim3(4, 4, 32), 128, SM1>>>(zAh + p * SQS, zAl + p * SQS, 65536,
                m3Th, m3Tl, 65536, 256,
                NF, 0, 0, zAh + q2 * SQS, zAl + q2 * SQS, 65536,
                zTh + q2 * SQS, zTl + q2 * SQS, 65536,
                zAh + p * SQS, zAl + p * SQS, 65536, 3.25f, -0.25f, NF, NF);
        } else {
            tg<1, 3><<<dim3(4, 4, 32), 128, SM3>>>(a2h, a2l, 65536,
                zTh + p * SQS, zTl + p * SQS, 65536, 256,
                NF, 0, 0, xzAh, xzAl, 65536, xzTh, xzTl, 65536, NB, NB, 0, 0.f, 1.f, NF, NF);
            tg<1, 3><<<dim3(4, 4, 32), 128, SM3>>>(xzAh, xzAl, 65536, xzTh, xzTl, 65536, 256,
                NF, 0, 0, NB, NB, 0, m1Th, m1Tl, 65536, xzAh, xzAl, 65536, 7.f, -1.f, NF, NF);
            tg<1, 3><<<dim3(4, 4, 32), 128, SM3>>>(xzAh, xzAl, 65536, m1Th, m1Tl, 65536, 256,
                NF, 0, 0, NB, NB, 0, m3Th, m3Tl, 65536, xzAh, xzAl, 65536, 15.f, -1.f, NF, NF);
            tg<1, 3><<<dim3(4, 4, 32), 128, SM3>>>(zAh + p * SQS, zAl + p * SQS, 65536,
                m3Th, m3Tl, 65536, 256,
                NF, 0, 0, zAh + q2 * SQS, zAl + q2 * SQS, 65536,
                zTh + q2 * SQS, zTl + q2 * SQS, 65536,
                zAh + p * SQS, zAl + p * SQS, 65536, 3.25f, -0.25f, NF, NF);
        }
    }
    // a3v^T = (a3 @ v)^T : 2-term
    tg<1, 2><<<dim3(1, 4, 32), 128, SM2>>>(a3h, NB, 1048576, vTh, vTl, 262144, 4096,
        NF, 0, 0, NB, NB, 0, avTh, avTl, 16384, NB, NB, 0, 0.f, 1.f, NF, NF);
    // w^T = (z @ a3v)^T : reassociated chain. 3-term (tiny). A=zA, B=avT. T-form out.
    tg<1, 3><<<dim3(1, 4, 32), 128, SM3>>>(zAh, zAl, 65536, avTh, avTl, 16384, 256,
        NF, 0, 0, NB, NB, 0, wTh, wTl, 16384, NB, NB, 0, 0.f, 1.f, NF, NF);
    // oh = a1 @ w : 2-term (a1 hi, wT split), fp32 out
    tg<0, 2><<<dim3(1, 64, 32), 128, SM2>>>(a1h, NB, 1048576, wTh, wTl, 16384, 256,
        ohA, 262144, 64, NB, NB, 0, NB, NB, 0, NB, NB, 0, 0.f, 1.f, NF, NF);
    // conv residual + gather + convert (fused)
    conv_k<<<dim3(128, 32), dim3(64, 8)>>>(wconv);
    // out = oh @ wout + bias + x : 2-term
    tg<4, 2><<<dim3(8, 256, 1), 128, SM2>>>(ohh, NB, 0, woTh, woTl, 0, 512,
        out, 0, 512, NB, NB, 0, NB, NB, 0, NB, NB, 0, 0.f, 1.f, x, bout);
}

// round 16
// speedup vs baseline: 1.1793x; 1.0205x over previous
#include <cuda_runtime.h>
#include <cuda_bf16.h>
#include <cstdint>
typedef long long ll;
typedef __nv_bfloat16 bf;

#define QS  8388608ll
#define LS  524288ll
#define A1S 33554432ll
#define SQS 2097152ll
#define XNS 8388608ll

__device__ __forceinline__ uint32_t smem_u32(const void* p) {
    uint32_t a;
    asm("{ .reg .u64 t; cvta.to.shared.u64 t, %1; cvt.u32.u64 %0, t; }" : "=r"(a) : "l"(p));
    return a;
}
#define LDM4(r, a) asm volatile("ldmatrix.sync.aligned.m8n8.x4.shared.b16 {%0,%1,%2,%3}, [%4];" \
    : "=r"((r)[0]), "=r"((r)[1]), "=r"((r)[2]), "=r"((r)[3]) : "r"(a))
#define MMA(c, a, b0, b1) asm volatile( \
    "mma.sync.aligned.m16n8k16.row.col.f32.bf16.bf16.f32 " \
    "{%0,%1,%2,%3}, {%4,%5,%6,%7}, {%8,%9}, {%0,%1,%2,%3};" \
    : "+f"((c)[0]), "+f"((c)[1]), "+f"((c)[2]), "+f"((c)[3]) \
    : "r"((a)[0]), "r"((a)[1]), "r"((a)[2]), "r"((a)[3]), "r"(b0), "r"(b1))
#define CPA(d, s) asm volatile("cp.async.cg.shared.global [%0], [%1], 16;" :: "r"(d), "l"(s))
#define CPC() asm volatile("cp.async.commit_group;")
#define CPW(n) asm volatile("cp.async.wait_group %0;" :: "n"(n))

__device__ __forceinline__ void splitf(float v, bf& h, bf& l) {
    h = __float2bfloat16(v);
    l = __float2bfloat16(v - __bfloat162float(h));
}

// ---------- scratch ----------
__device__ bf g_xnh[XNS];
__device__ bf g_wqTh[786432], g_wqTl[786432], g_woTh[262144], g_woTl[262144];
__device__ bf g_qh[QS], g_kh[QS], g_klo[QS], g_vTh[QS], g_vTl[QS];
__device__ bf g_lqh[LS], g_lql[LS], g_lkh[LS], g_lkl[LS];
__device__ bf g_a1h[A1S], g_a3h[A1S];
__device__ float g_a2f[SQS];
__device__ bf g_a2h[SQS], g_a2l[SQS];
__device__ bf g_xzAh[SQS], g_xzAl[SQS], g_xzTh[SQS], g_xzTl[SQS];
__device__ bf g_m1Th[SQS], g_m1Tl[SQS], g_m3Th[SQS], g_m3Tl[SQS];
__device__ bf g_zAh[2 * SQS], g_zAl[2 * SQS], g_zTh[2 * SQS], g_zTl[2 * SQS];
__device__ bf g_avTh[LS], g_avTl[LS];
__device__ bf g_wTh[LS], g_wTl[LS];
__device__ float g_ohA[QS];
__device__ bf g_ohh[XNS];
__device__ int g_redi[2];

// ---------- reductions ----------
__device__ __forceinline__ float wrs(float v) {
    #pragma unroll
    for (int o = 16; o; o >>= 1) v += __shfl_xor_sync(0xffffffffu, v, o);
    return v;
}
__device__ __forceinline__ float wrm(float v) {
    #pragma unroll
    for (int o = 16; o; o >>= 1) v = fmaxf(v, __shfl_xor_sync(0xffffffffu, v, o));
    return v;
}
__device__ __forceinline__ float brs(float v) {
    __shared__ float sm[32];
    int lane = threadIdx.x & 31, w = threadIdx.x >> 5;
    __syncthreads();
    v = wrs(v);
    if (!lane) sm[w] = v;
    __syncthreads();
    float r = (threadIdx.x < (blockDim.x >> 5)) ? sm[threadIdx.x] : 0.f;
    if (w == 0) { r = wrs(r); if (!lane) sm[0] = r; }
    __syncthreads();
    return sm[0];
}
__device__ __forceinline__ float brm(float v) {
    __shared__ float sm[32];
    int lane = threadIdx.x & 31, w = threadIdx.x >> 5;
    __syncthreads();
    v = wrm(v);
    if (!lane) sm[w] = v;
    __syncthreads();
    float r = (threadIdx.x < (blockDim.x >> 5)) ? sm[threadIdx.x] : -3.4e38f;
    if (w == 0) { r = wrm(r); if (!lane) sm[0] = r; }
    __syncthreads();
    return sm[0];
}

// ====== HMMA GEMM, cp.async double-buffered, term-major MMA order ======
// NT=1: Ah*Bh.  NT=2: Ah*Bh + Ah*Bl.  NT=3: + Al*Bh.
// KIND 0: fp32 C.  1: f = c1*X + c2*acc -> bf16 A-form (hi[,lo]) and/or T-form.
//   (X lo-plane read only when Xl != null)
// 3: QKV scatter.  4: acc + bias + residual -> fp32.
#define STR 144
template<int KIND, int NT>
__global__ __launch_bounds__(128) void tg(
    const bf* __restrict__ Ah, const bf* __restrict__ Al, ll sA,
    const bf* __restrict__ Bh, const bf* __restrict__ Bl, ll sB, int K,
    float* __restrict__ Cf, ll sC, int ldc,
    bf* __restrict__ Oh, bf* __restrict__ Ol, ll sO,
    bf* __restrict__ Th, bf* __restrict__ Tl, ll sT,
    const bf* __restrict__ Xh, const bf* __restrict__ Xl, ll sX, float c1, float c2,
    const float* __restrict__ Rf, const float* __restrict__ bias)
{
    constexpr int NARR = (NT == 3) ? 4 : (NT == 2) ? 3 : 2;
    constexpr int SSTG = NARR * 64 * STR;
    constexpr int OAL = 64 * STR;
    constexpr int OBH = (NT == 3 ? 2 : 1) * 64 * STR;
    constexpr int OBL = OBH + 64 * STR;
    extern __shared__ __align__(16) unsigned char sm_[];
    uint32_t sb = smem_u32(sm_);
    int tid = threadIdx.x, wid = tid >> 5, lane = tid & 31;
    int wy = wid >> 1, wx = wid & 1;
    int m0 = blockIdx.y * 64, n0 = blockIdx.x * 64, bz = blockIdx.z;
    Ah += (ll)bz * sA;
    if (NT == 3) Al += (ll)bz * sA;
    Bh += (ll)bz * sB;
    if (NT >= 2) Bl += (ll)bz * sB;
    float acc[2][4][4] = {};
    int row8 = tid >> 3, c8 = tid & 7;
    int nch = K >> 6;

    auto loadStage = [&](int c, int stg) {
        int k0 = c << 6;
        uint32_t base = sb + stg * SSTG;
        #pragma unroll
        for (int i = 0; i < 4; i++) {
            int r = row8 + i * 16;
            uint32_t so = r * STR + c8 * 16;
            ll ga = (ll)(m0 + r) * K + k0 + c8 * 8;
            ll gb = (ll)(n0 + r) * K + k0 + c8 * 8;
            CPA(base + so, Ah + ga);
            CPA(base + OBH + so, Bh + gb);
            if (NT == 3) CPA(base + OAL + so, Al + ga);
            if (NT >= 2) CPA(base + OBL + so, Bl + gb);
        }
    };
    loadStage(0, 0);
    CPC();
    for (int c = 0; c < nch; c++) {
        if (c + 1 < nch) { loadStage(c + 1, (c + 1) & 1); CPC(); CPW(1); }
        else CPW(0);
        __syncthreads();
        uint32_t bs = sb + (c & 1) * SSTG;
        #pragma unroll
        for (int s = 0; s < 4; s++) {
            uint32_t aH[2][4], aL[2][4], bH[4][2], bL[4][2];
            #pragma unroll
            for (int mt = 0; mt < 2; mt++) {
                uint32_t ad = bs + (wy * 32 + mt * 16 + (lane & 15)) * STR + s * 32 + (lane >> 4) * 16;
                LDM4(aH[mt], ad);
                if (NT == 3) LDM4(aL[mt], ad + OAL);
            }
            #pragma unroll
            for (int np = 0; np < 2; np++) {
                uint32_t bd = bs + OBH + (wx * 32 + np * 16 + (lane & 15)) * STR + s * 32 + (lane >> 4) * 16;
                uint32_t t0[4];
                LDM4(t0, bd);
                bH[2 * np][0] = t0[0]; bH[2 * np][1] = t0[2];
                bH[2 * np + 1][0] = t0[1]; bH[2 * np + 1][1] = t0[3];
                if (NT >= 2) {
                    uint32_t t1[4];
                    LDM4(t1, bd + (OBL - OBH));
                    bL[2 * np][0] = t1[0]; bL[2 * np][1] = t1[2];
                    bL[2 * np + 1][0] = t1[1]; bL[2 * np + 1][1] = t1[3];
                }
            }
            #pragma unroll
            for (int mt = 0; mt < 2; mt++)
                #pragma unroll
                for (int nt = 0; nt < 4; nt++)
                    MMA(acc[mt][nt], aH[mt], bH[nt][0], bH[nt][1]);
            if (NT >= 2) {
                #pragma unroll
                for (int mt = 0; mt < 2; mt++)
                    #pragma unroll
                    for (int nt = 0; nt < 4; nt++)
                        MMA(acc[mt][nt], aH[mt], bL[nt][0], bL[nt][1]);
            }
            if (NT == 3) {
                #pragma unroll
                for (int mt = 0; mt < 2; mt++)
                    #pragma unroll
                    for (int nt = 0; nt < 4; nt++)
                        MMA(acc[mt][nt], aL[mt], bH[nt][0], bH[nt][1]);
            }
        }
        __syncthreads();
    }

    float* cs = (float*)sm_ + wid * 1056;
    int g8 = lane >> 2, tg4 = lane & 3;
    #pragma unroll
    for (int mt = 0; mt < 2; mt++)
        #pragma unroll
        for (int nt = 0; nt < 4; nt++)
            #pragma unroll
            for (int ci = 0; ci < 4; ci++) {
                int r = mt * 16 + g8 + ((ci >> 1) & 1) * 8;
                int c = nt * 8 + tg4 * 2 + (ci & 1);
                cs[r * 33 + c] = acc[mt][nt][ci];
            }
    __syncwarp();
    int r0w = m0 + wy * 32, c0w = n0 + wx * 32;

    if constexpr (KIND == 0) {
        #pragma unroll
        for (int j = 0; j < 32; j++)
            Cf[(ll)bz * sC + (ll)(r0w + j) * ldc + c0w + lane] = cs[j * 33 + lane];
    }
    if constexpr (KIND == 1) {
        if (Xh) {
            int ldx = gridDim.x * 64;
            if (Xl) {
                #pragma unroll
                for (int j = 0; j < 32; j++) {
                    ll o = (ll)bz * sX + (ll)(r0w + j) * ldx + c0w + lane;
                    float xv = __bfloat162float(Xh[o]) + __bfloat162float(Xl[o]);
                    cs[j * 33 + lane] = c1 * xv + c2 * cs[j * 33 + lane];
                }
            } else {
                #pragma unroll
                for (int j = 0; j < 32; j++) {
                    ll o = (ll)bz * sX + (ll)(r0w + j) * ldx + c0w + lane;
                    float xv = __bfloat162float(Xh[o]);
                    cs[j * 33 + lane] = c1 * xv + c2 * cs[j * 33 + lane];
                }
            }
            __syncwarp();
        }
        if (Th) {
            int ldT = gridDim.y * 64;
            #pragma unroll
            for (int j = 0; j < 32; j++) {
                bf h, l; splitf(cs[lane * 33 + j], h, l);
                ll o = (ll)bz * sT + (ll)(c0w + j) * ldT + r0w + lane;
                Th[o] = h;
                if (Tl) Tl[o] = l;
            }
        }
        if (Oh) {
            int ldO = gridDim.x * 64;
            #pragma unroll
            for (int j = 0; j < 32; j++) {
                bf h, l; splitf(cs[j * 33 + lane], h, l);
                ll o = (ll)bz * sO + (ll)(r0w + j) * ldO + c0w + lane;
                Oh[o] = h;
                if (Ol) Ol[o] = l;
            }
        }
    }
    if constexpr (KIND == 3) {
        int part = c0w >> 9, hh = (c0w >> 6) & 7, d0 = c0w & 63;
        if (part == 2) {
            int b = r0w >> 12, nn = r0w & 4095;
            ll base = ((ll)(b * 8 + hh) * 64 + d0) * 4096 + nn + lane;
            #pragma unroll
            for (int j = 0; j < 32; j++) {
                bf h, l; splitf(cs[lane * 33 + j], h, l);
                g_vTh[base + (ll)j * 4096] = h;
                g_vTl[base + (ll)j * 4096] = l;
            }
        } else if (part == 1) {
            #pragma unroll
            for (int j = 0; j < 32; j++) {
                int rr = r0w + j, b = rr >> 12, nn = rr & 4095;
                bf h, l; splitf(cs[j * 33 + lane], h, l);
                ll o = ((ll)(b * 8 + hh) * 4096 + nn) * 64 + d0 + lane;
                g_kh[o] = h; g_klo[o] = l;
            }
        } else {
            #pragma unroll
            for (int j = 0; j < 32; j++) {
                int rr = r0w + j, b = rr >> 12, nn = rr & 4095;
                ll o = ((ll)(b * 8 + hh) * 4096 + nn) * 64 + d0 + lane;
                g_qh[o] = __float2bfloat16(cs[j * 33 + lane] * 0.125f);
            }
        }
    }
    if constexpr (KIND == 4) {
        float bv = bias[c0w + lane];
        #pragma unroll
        for (int j = 0; j < 32; j++) {
            ll o = (ll)(r0w + j) * ldc + c0w + lane;
            Cf[o] = cs[j * 33 + lane] + bv + Rf[o];
        }
    }
}

// ---------------- small kernels ----------------
__global__ __launch_bounds__(256) void ln_k(const float* __restrict__ x,
                                            const float* __restrict__ w,
                                            const float* __restrict__ b) {
    ll base = (ll)blockIdx.x * 512;
    int t = threadIdx.x;
    float v0 = x[base + t], v1 = x[base + 256 + t];
    float mu = brs(v0 + v1) * (1.f / 512.f);
    float d0 = v0 - mu, d1 = v1 - mu;
    float var = brs(d0 * d0 + d1 * d1) * (1.f / 512.f);
    float r = rsqrtf(var + 1e-5f);
    g_xnh[base + t]       = __float2bfloat16(d0 * r * w[t] + b[t]);
    g_xnh[base + 256 + t] = __float2bfloat16(d1 * r * w[256 + t] + b[256 + t]);
}

__global__ void wtrans_k(const float* __restrict__ X, int R, int C, bf* Oh, bf* Ol) {
    __shared__ float t[32][33];
    int c0 = blockIdx.x * 32, r0 = blockIdx.y * 32, tx = threadIdx.x;
    for (int r = threadIdx.y; r < 32; r += 8) t[r][tx] = X[(ll)(r0 + r) * C + c0 + tx];
    __syncthreads();
    for (int r = threadIdx.y; r < 32; r += 8) {
        bf h, l; splitf(t[tx][r], h, l);
        ll o = (ll)(c0 + r) * R + r0 + tx;
        Oh[o] = h; Ol[o] = l;
    }
}

__global__ void landmark_k() {
    int m = blockIdx.x, bh = blockIdx.y, d = threadIdx.x;
    ll base = ((ll)bh * 4096 + m * 16) * 64 + d;
    float sq = 0.f, sk = 0.f;
    #pragma unroll
    for (int j = 0; j < 16; j++) {
        ll o = base + (ll)j * 64;
        sq += __bfloat162float(g_qh[o]);
        sk += __bfloat162float(g_kh[o]) + __bfloat162float(g_klo[o]);
    }
    ll o = ((ll)bh * 256 + m) * 64 + d;
    bf h, l;
    splitf(sq * 0.0625f, h, l); g_lqh[o] = h; g_lql[o] = l;
    splitf(sk * 0.0625f, h, l); g_lkh[o] = h; g_lkl[o] = l;
}

// in-place bf16 softmax over rows of 256 (a1h)
__global__ __launch_bounds__(256) void sm256a1_k() {
    ll base = (ll)blockIdx.x * 256;
    int t = threadIdx.x;
    float v = __bfloat162float(g_a1h[base + t]);
    float m = brm(v);
    float e = __expf(v - m);
    float s = brs(e);
    g_a1h[base + t] = __float2bfloat16(e / s);
}
__global__ __launch_bounds__(256) void sm256a2_k() {
    ll base = (ll)blockIdx.x * 256;
    int t = threadIdx.x;
    float v = g_a2f[base + t];
    float m = brm(v);
    float e = __expf(v - m);
    float s = brs(e);
    float r = e / s;
    g_a2f[base + t] = r;
    bf h, l; splitf(r, h, l);
    g_a2h[base + t] = h; g_a2l[base + t] = l;
}
// in-place bf16 softmax over rows of 4096 (a3h)
__global__ __launch_bounds__(256) void sm4096_k() {
    ll base = (ll)blockIdx.x * 4096;
    int t = threadIdx.x;
    float v[16], m = -3.4e38f;
    #pragma unroll
    for (int i = 0; i < 16; i++) {
        v[i] = __bfloat162float(g_a3h[base + t + i * 256]);
        m = fmaxf(m, v[i]);
    }
    m = brm(m);
    float s = 0.f;
    #pragma unroll
    for (int i = 0; i < 16; i++) { v[i] = __expf(v[i] - m); s += v[i]; }
    s = 1.f / brs(s);
    #pragma unroll
    for (int i = 0; i < 16; i++)
        g_a3h[base + t + i * 256] = __float2bfloat16(v[i] * s);
}

__global__ void reset_k() { g_redi[0] = 0; g_redi[1] = 0; }
__global__ __launch_bounds__(256) void rowsum_k() {
    const float* r = g_a2f + ((ll)blockIdx.x * 256 + threadIdx.x) * 256;
    float s = 0.f;
    for (int j = 0; j < 256; j++) s += r[j];
    s = brm(s);
    if (threadIdx.x == 0) atomicMax(&g_redi[0], __float_as_int(s));
}
__global__ __launch_bounds__(256) void colsum_k() {
    const float* b = g_a2f + (ll)blockIdx.x * 65536 + threadIdx.x;
    float s = 0.f;
    for (int i = 0; i < 256; i++) s += b[i * 256];
    s = brm(s);
    if (threadIdx.x == 0) atomicMax(&g_redi[1], __float_as_int(s));
}
__global__ void zinit_k() {
    __shared__ float t[32][33];
    int bh = blockIdx.z, i0 = blockIdx.y * 32, j0 = blockIdx.x * 32, tx = threadIdx.x;
    const float* a = g_a2f + (ll)bh * 65536;
    float sc = 1.f / (__int_as_float(g_redi[0]) * __int_as_float(g_redi[1]));
    for (int r = threadIdx.y; r < 32; r += 8) {
        float v = a[(ll)(i0 + r) * 256 + j0 + tx];
        t[r][tx] = v;
        bf h, l; splitf(v * sc, h, l);
        ll o = (ll)bh * 65536 + (ll)(i0 + r) * 256 + j0 + tx;
        g_zTh[o] = h; g_zTl[o] = l;
    }
    __syncthreads();
    for (int r = threadIdx.y; r < 32; r += 8) {
        bf h, l; splitf(t[tx][r] * sc, h, l);
        ll o = (ll)bh * 65536 + (ll)(j0 + r) * 256 + i0 + tx;
        g_zAh[o] = h; g_zAl[o] = l;
    }
}

// conv residual fused with gather+convert: ohh = gathered(ohA + conv(v)), hi only
__global__ __launch_bounds__(512) void conv_k(const float* __restrict__ wc) {
    __shared__ float sv[64][65];
    __shared__ float sw[33];
    int bh = blockIdx.y, h = bh & 7, n0 = blockIdx.x * 32;
    int tx = threadIdx.x, ty = threadIdx.y;
    int lt = ty * 64 + tx;
    if (lt < 33) sw[lt] = wc[h * 33 + lt];
    ll vb = (ll)bh * 262144;
    for (int dd = 0; dd < 8; dd++) {
        int d = dd * 8 + ty, n = n0 - 16 + tx;
        float v = 0.f;
        if (n >= 0 && n < 4096) {
            ll o = vb + (ll)d * 4096 + n;
            v = __bfloat162float(g_vTh[o]) + __bfloat162float(g_vTl[o]);
        }
        sv[d][tx] = v;
    }
    __syncthreads();
    ll rowb = (ll)((bh >> 3) * 4096 + n0) * 512 + h * 64 + tx;
    for (int k = 0; k < 4; k++) {
        int nl = ty * 4 + k;
        float acc = 0.f;
        #pragma unroll
        for (int t = 0; t < 33; t++) acc += sv[tx][nl + t] * sw[t];
        float o = g_ohA[vb + (ll)(n0 + nl) * 64 + tx] + acc;
        g_ohh[rowb + (ll)nl * 512] = __float2bfloat16(o);
    }
}

// ---------------- launch ----------------
#define GSA(p, s) cudaGetSymbolAddress((void**)&p, s)
#define NB (bf*)nullptr
#define NF (float*)nullptr
#define SM3 73728
#define SM2 55296
#define SM1 36864

extern "C" void kernel_launch(void* const* d_in, const int* in_sizes, int n_in,
                              void* d_out, int out_size) {
    const float* x = (const float*)d_in[0];
    const float* lnw = (const float*)d_in[1];
    const float* lnb = (const float*)d_in[2];
    const float* wqkv = (const float*)d_in[3];
    const float* wout = (const float*)d_in[4];
    const float* bout = (const float*)d_in[5];
    const float* wconv = (const float*)d_in[6];
    float* out = (float*)d_out;

    static bool init = false;
    static bf *xnh, *wqTh, *wqTl, *woTh, *woTl, *qh, *kh, *kl, *vTh, *vTl;
    static bf *lqh, *lql, *lkh, *lkl, *a1h, *a3h;
    static bf *a2h, *a2l, *xzAh, *xzAl, *xzTh, *xzTl, *m1Th, *m1Tl, *m3Th, *m3Tl;
    static bf *zAh, *zAl, *zTh, *zTl, *avTh, *avTl, *wTh, *wTl, *ohh;
    static float *a2f, *ohA;
    if (!init) {
        init = true;
        GSA(xnh, g_xnh); GSA(wqTh, g_wqTh); GSA(wqTl, g_wqTl);
        GSA(woTh, g_woTh); GSA(woTl, g_woTl); GSA(qh, g_qh);
        GSA(kh, g_kh); GSA(kl, g_klo); GSA(vTh, g_vTh); GSA(vTl, g_vTl);
        GSA(lqh, g_lqh); GSA(lql, g_lql); GSA(lkh, g_lkh); GSA(lkl, g_lkl);
        GSA(a1h, g_a1h); GSA(a3h, g_a3h);
        GSA(a2h, g_a2h); GSA(a2l, g_a2l);
        GSA(xzAh, g_xzAh); GSA(xzAl, g_xzAl); GSA(xzTh, g_xzTh); GSA(xzTl, g_xzTl);
        GSA(m1Th, g_m1Th); GSA(m1Tl, g_m1Tl); GSA(m3Th, g_m3Th); GSA(m3Tl, g_m3Tl);
        GSA(zAh, g_zAh); GSA(zAl, g_zAl); GSA(zTh, g_zTh); GSA(zTl, g_zTl);
        GSA(avTh, g_avTh); GSA(avTl, g_avTl); GSA(wTh, g_wTh); GSA(wTl, g_wTl);
        GSA(ohh, g_ohh);
        GSA(a2f, g_a2f); GSA(ohA, g_ohA);
        cudaFuncSetAttribute(tg<3, 2>, cudaFuncAttributeMaxDynamicSharedMemorySize, SM2);
        cudaFuncSetAttribute(tg<0, 3>, cudaFuncAttributeMaxDynamicSharedMemorySize, SM3);
        cudaFuncSetAttribute(tg<1, 3>, cudaFuncAttributeMaxDynamicSharedMemorySize, SM3);
        cudaFuncSetAttribute(tg<1, 2>, cudaFuncAttributeMaxDynamicSharedMemorySize, SM2);
        cudaFuncSetAttribute(tg<0, 2>, cudaFuncAttributeMaxDynamicSharedMemorySize, SM2);
        cudaFuncSetAttribute(tg<1, 1>, cudaFuncAttributeMaxDynamicSharedMemorySize, SM1);
        cudaFuncSetAttribute(tg<4, 2>, cudaFuncAttributeMaxDynamicSharedMemorySize, SM2);
    }

    ln_k<<<16384, 256>>>(x, lnw, lnb);
    wtrans_k<<<dim3(48, 16), dim3(32, 8)>>>(wqkv, 512, 1536, wqTh, wqTl);
    wtrans_k<<<dim3(16, 16), dim3(32, 8)>>>(wout, 512, 512, woTh, woTl);
    // QKV projection (2-term) with scatter epilogue
    tg<3, 2><<<dim3(24, 256, 1), 128, SM2>>>(xnh, NB, 0, wqTh, wqTl, 0, 512,
        NF, 0, 0, NB, NB, 0, NB, NB, 0, NB, NB, 0, 0.f, 1.f, NF, NF);
    landmark_k<<<dim3(256, 32), 64>>>();
    // sim1 (2-term) -> bf16 logits in a1h -> in-place softmax
    tg<1, 2><<<dim3(4, 64, 32), 128, SM2>>>(qh, NB, 262144, lkh, lkl, 16384, 64,
        NF, 0, 0, a1h, NB, 1048576, NB, NB, 0, NB, NB, 0, 0.f, 1.f, NF, NF);
    sm256a1_k<<<131072, 256>>>();
    // sim2 (3-term, feeds pinv) -> fp32 -> softmax -> a2 hi/lo
    tg<0, 3><<<dim3(4, 4, 32), 128, SM3>>>(lqh, lql, 16384, lkh, lkl, 16384, 64,
        a2f, 65536, 256, NB, NB, 0, NB, NB, 0, NB, NB, 0, 0.f, 1.f, NF, NF);
    sm256a2_k<<<8192, 256>>>();
    // sim3 (2-term) -> bf16 logits in a3h -> in-place softmax
    tg<1, 2><<<dim3(64, 4, 32), 128, SM2>>>(lqh, NB, 16384, kh, kl, 262144, 64,
        NF, 0, 0, a3h, NB, 1048576, NB, NB, 0, NB, NB, 0, 0.f, 1.f, NF, NF);
    sm4096_k<<<8192, 256>>>();
    reset_k<<<1, 1>>>();
    rowsum_k<<<32, 256>>>();
    colsum_k<<<32, 256>>>();
    zinit_k<<<dim3(8, 8, 32), dim3(32, 8)>>>();
    // Newton-Schulz: iters 0-4 plain bf16 with dead lo-planes elided
    // (hi-only X reads; lo outputs only where consumed: iter4's z-update
    //  feeds iter5's 3-term B and hi/lo X). Iter 5 full 3-term. z -> slot 0.
    for (int it = 0; it < 6; it++) {
        int p = it & 1, q2 = 1 - p;
        if (it < 5) {
            bool last = (it == 4);
            tg<1, 1><<<dim3(4, 4, 32), 128, SM1>>>(a2h, NB, 65536,
                zTh + p * SQS, NB, 65536, 256,
                NF, 0, 0, xzAh, NB, 65536, xzTh, NB, 65536, NB, NB, 0, 0.f, 1.f, NF, NF);
            tg<1, 1><<<dim3(4, 4, 32), 128, SM1>>>(xzAh, NB, 65536, xzTh, NB, 65536, 256,
                NF, 0, 0, NB, NB, 0, m1Th, NB, 65536, xzAh, NB, 65536, 7.f, -1.f, NF, NF);
            tg<1, 1><<<dim3(4, 4, 32), 128, SM1>>>(xzAh, NB, 65536, m1Th, NB, 65536, 256,
                NF, 0, 0, NB, NB, 0, m3Th, NB, 65536, xzAh, NB, 65536, 15.f, -1.f, NF, NF);
            tg<1, 1><<<dim3(4, 4, 32), 128, SM1>>>(zAh + p * SQS, NB, 65536,
                m3Th, NB, 65536, 256,
                NF, 0, 0, zAh + q2 * SQS, last ? (zAl + q2 * SQS) : NB, 65536,
                zTh + q2 * SQS, last ? (zTl + q2 * SQS) : NB, 65536,
                zAh + p * SQS, NB, 65536, 3.25f, -0.25f, NF, NF);
        } else {
            tg<1, 3><<<dim3(4, 4, 32), 128, SM3>>>(a2h, a2l, 65536,
                zTh + p * SQS, zTl + p * SQS, 65536, 256,
                NF, 0, 0, xzAh, xzAl, 65536, xzTh, xzTl, 65536, NB, NB, 0, 0.f, 1.f, NF, NF);
            tg<1, 3><<<dim3(4, 4, 32), 128, SM3>>>(xzAh, xzAl, 65536, xzTh, xzTl, 65536, 256,
                NF, 0, 0, NB, NB, 0, m1Th, m1Tl, 65536, xzAh, xzAl, 65536, 7.f, -1.f, NF, NF);
            tg<1, 3><<<dim3(4, 4, 32), 128, SM3>>>(xzAh, xzAl, 65536, m1Th, m1Tl, 65536, 256,
                NF, 0, 0, NB, NB, 0, m3Th, m3Tl, 65536, xzAh, xzAl, 65536, 15.f, -1.f, NF, NF);
            tg<1, 3><<<dim3(4, 4, 32), 128, SM3>>>(zAh + p * SQS, zAl + p * SQS, 65536,
                m3Th, m3Tl, 65536, 256,
                NF, 0, 0, zAh + q2 * SQS, zAl + q2 * SQS, 65536,
                zTh + q2 * SQS, zTl + q2 * SQS, 65536,
                zAh + p * SQS, zAl + p * SQS, 65536, 3.25f, -0.25f, NF, NF);
        }
    }
    // a3v^T = (a3 @ v)^T : 2-term
    tg<1, 2><<<dim3(1, 4, 32), 128, SM2>>>(a3h, NB, 1048576, vTh, vTl, 262144, 4096,
        NF, 0, 0, NB, NB, 0, avTh, avTl, 16384, NB, NB, 0, 0.f, 1.f, NF, NF);
    // w^T = (z @ a3v)^T : reassociated chain. 3-term (tiny). T-form out.
    tg<1, 3><<<dim3(1, 4, 32), 128, SM3>>>(zAh, zAl, 65536, avTh, avTl, 16384, 256,
        NF, 0, 0, NB, NB, 0, wTh, wTl, 16384, NB, NB, 0, 0.f, 1.f, NF, NF);
    // oh = a1 @ w : 2-term (a1 hi, wT split), fp32 out
    tg<0, 2><<<dim3(1, 64, 32), 128, SM2>>>(a1h, NB, 1048576, wTh, wTl, 16384, 256,
        ohA, 262144, 64, NB, NB, 0, NB, NB, 0, NB, NB, 0, 0.f, 1.f, NF, NF);
    // conv residual + gather + convert (fused)
    conv_k<<<dim3(128, 32), dim3(64, 8)>>>(wconv);
    // out = oh @ wout + bias + x : 2-term
    tg<4, 2><<<dim3(8, 256, 1), 128, SM2>>>(ohh, NB, 0, woTh, woTl, 0, 512,
        out, 0, 512, NB, NB, 0, NB, NB, 0, NB, NB, 0, 0.f, 1.f, x, bout);
}